// round 12
// baseline (speedup 1.0000x reference)
#include <cuda_runtime.h>
#include <cuda_fp16.h>
#include <math.h>
#include <stdint.h>

#define BATCH   32
#define SEQ     197
#define EMB     768
#define EMB3    2304
#define HEADS   12
#define HD      64
#define KW      197
#define NLAYERS 12
#define HIDDEN  3072
#define TOK     (BATCH*SEQ)       // 6304
#define BH      (BATCH*HEADS)     // 384
#define ROWSA   (BH*SEQ)          // 75648
#define SPAD    224
#define KWPAD   208

#define CDIV(a,b) (((a)+(b)-1)/(b))

// ---------------- scratch ----------------
static __device__ float  g_x1 [TOK*EMB];
static __device__ float  g_x2 [TOK*EMB];
static __device__ __half g_xn [TOK*EMB];
static __device__ __half g_qkv[TOK*EMB3];
static __device__ __half g_S  [(size_t)BH*SEQ*SPAD];
static __device__ __half g_A  [(size_t)BH*SEQ*SPAD];
static __device__ __half g_y  [BH*KW*HD];
static __device__ __half g_h  [TOK*HIDDEN];
static __device__ __half g_wqkv [EMB3*EMB];
static __device__ __half g_wfc  [256*SPAD];
static __device__ __half g_w1   [HIDDEN*EMB];
static __device__ __half g_w2   [EMB*HIDDEN];
static __device__ __half g_wfc2t[256*KWPAD];

// ---------------- helpers ----------------
__device__ __forceinline__ void cpasync16(uint32_t dst, const void* src, int srcbytes) {
    asm volatile("cp.async.cg.shared.global [%0], [%1], 16, %2;\n"
                 :: "r"(dst), "l"(src), "r"(srcbytes));
}
__device__ __forceinline__ void cp_commit() { asm volatile("cp.async.commit_group;\n"); }
__device__ __forceinline__ void cp_wait0() { asm volatile("cp.async.wait_group 0;\n"); }
__device__ __forceinline__ void cp_wait1() { asm volatile("cp.async.wait_group 1;\n"); }

#define MMA_F16(acc, afr, bfr)                                               \
    asm volatile(                                                            \
        "mma.sync.aligned.m16n8k16.row.col.f32.f16.f16.f32 "                 \
        "{%0,%1,%2,%3}, {%4,%5,%6,%7}, {%8,%9}, {%0,%1,%2,%3};\n"            \
        : "+f"((acc)[0]), "+f"((acc)[1]), "+f"((acc)[2]), "+f"((acc)[3])     \
        : "r"((afr)[0]), "r"((afr)[1]), "r"((afr)[2]), "r"((afr)[3]),        \
          "r"((bfr)[0]), "r"((bfr)[1]))

#define LDSM_X4(r0, r1, r2, r3, addr)                                        \
    asm volatile("ldmatrix.sync.aligned.m8n8.x4.shared.b16 "                 \
                 "{%0,%1,%2,%3}, [%4];"                                      \
                 : "=r"(r0), "=r"(r1), "=r"(r2), "=r"(r3) : "r"(addr))

#define LDSM_X4_T(r0, r1, r2, r3, addr)                                      \
    asm volatile("ldmatrix.sync.aligned.m8n8.x4.trans.shared.b16 "           \
                 "{%0,%1,%2,%3}, [%4];"                                      \
                 : "=r"(r0), "=r"(r1), "=r"(r2), "=r"(r3) : "r"(addr))

// ---------------- elementwise / prep ----------------
__global__ void init_copy(const float* __restrict__ x, float* __restrict__ x1,
                          float* __restrict__ x2, int n) {
    int i = blockIdx.x * blockDim.x + threadIdx.x;
    if (i < n) { float v = x[i]; x1[i] = v; x2[i] = v; }
}

__global__ void finalize_k(const float* __restrict__ x1, const float* __restrict__ x2,
                           float* __restrict__ out, int n) {
    int i = blockIdx.x * blockDim.x + threadIdx.x;
    if (i < n) out[i] = 0.5f * (x1[i] + x2[i]);
}

__global__ void prep_wT(const float* __restrict__ s, __half* __restrict__ d,
                        int K, int N) {
    int i = blockIdx.x * blockDim.x + threadIdx.x;
    if (i < N * K) {
        int n = i / K, k = i % K;
        d[i] = __float2half_rn(s[(size_t)k * N + n]);
    }
}

__global__ void prep_fcT(const float* __restrict__ s, __half* __restrict__ d) {
    int i = blockIdx.x * blockDim.x + threadIdx.x;
    if (i < 256 * SPAD) {
        int n = i / SPAD, k = i % SPAD;
        d[i] = (n < KW && k < SEQ) ? __float2half_rn(s[k * KW + n]) : __float2half(0.f);
    }
}

__global__ void prep_fc2T(const float* __restrict__ s, __half* __restrict__ d) {
    int i = blockIdx.x * blockDim.x + threadIdx.x;
    if (i < 256 * KWPAD) {
        int n2 = i / KWPAD, k = i % KWPAD;
        d[i] = (n2 < SEQ && k < KW) ? __float2half_rn(s[k * SEQ + n2]) : __float2half(0.f);
    }
}

__global__ void zero_pad_S(__half* __restrict__ S) {
    int i = blockIdx.x * blockDim.x + threadIdx.x;
    const int padw = SPAD - KW;
    if (i < ROWSA * padw) {
        int r = i / padw, c = KW + i % padw;
        S[(size_t)r * SPAD + c] = __float2half(0.f);
    }
}

// ---------------- layernorm rows of 768 -> half ----------------
__global__ void ln_row768(const float* __restrict__ x, const float* __restrict__ g,
                          const float* __restrict__ b, __half* __restrict__ out) {
    int row = blockIdx.x;
    const float* xr = x + (size_t)row * EMB;
    __half* orow = out + (size_t)row * EMB;
    int tid = threadIdx.x;
    float s = 0.f, ss = 0.f;
    for (int i = tid; i < EMB; i += 256) { float v = xr[i]; s += v; ss += v * v; }
    __shared__ float rs[8], rss[8];
    #pragma unroll
    for (int o = 16; o; o >>= 1) {
        s  += __shfl_xor_sync(0xffffffffu, s,  o);
        ss += __shfl_xor_sync(0xffffffffu, ss, o);
    }
    if ((tid & 31) == 0) { rs[tid >> 5] = s; rss[tid >> 5] = ss; }
    __syncthreads();
    if (tid < 32) {
        float a = (tid < 8) ? rs[tid]  : 0.f;
        float c = (tid < 8) ? rss[tid] : 0.f;
        #pragma unroll
        for (int o = 4; o; o >>= 1) {
            a += __shfl_xor_sync(0xffffffffu, a, o);
            c += __shfl_xor_sync(0xffffffffu, c, o);
        }
        if (tid == 0) { rs[0] = a; rss[0] = c; }
    }
    __syncthreads();
    float mu  = rs[0] * (1.0f / EMB);
    float var = rss[0] * (1.0f / EMB) - mu * mu;
    float inv = rsqrtf(var + 1e-5f);
    for (int i = tid; i < EMB; i += 256)
        orow[i] = __float2half_rn((xr[i] - mu) * inv * g[i] + b[i]);
}

// ================= fp16 GEMM, 64x64 warp tiles =============================
// C[M,N] = A[M,K] @ Bt[N,K]^T. CTA 128x128x32, 4 warps (2m x 2n) of 64x64,
// 3-stage cp.async pipeline, ldmatrix fragments, dynamic smem (60 KB).
// Requires K % 32 == 0 and K >= 64 (all call sites satisfy this).
// EPI: 1 +bias->half | 2 +bias,gelu->half | 3 +bias,+res->float | 4 ->half
#define GST   40                 // smem row stride in halfs
#define GSTGB (128*GST)          // one stage (A or B) in halfs (5120)
#define GB_SMEM (6*GSTGB*2)      // 3 stages x (A+B) in bytes = 61440

template <int EPI>
__global__ void __launch_bounds__(128) gemm_big(
    const __half* __restrict__ A, const __half* __restrict__ B,
    const float* __restrict__ bias, const float* __restrict__ res,
    __half* __restrict__ Ch, float* __restrict__ Cf,
    int ldc, int M, int N, int K)
{
    extern __shared__ __half smg[];
    __half* As = smg;                    // 3 * GSTGB
    __half* Bs = smg + 3 * GSTGB;        // 3 * GSTGB
    const int tid  = threadIdx.x;
    const int warp = tid >> 5, lane = tid & 31;
    const int wm = warp >> 1, wn = warp & 1;
    const int g = lane >> 2, t = lane & 3;
    const int m0 = blockIdx.y * 128, n0 = blockIdx.x * 128;

    const uint32_t as_u = (uint32_t)__cvta_generic_to_shared(As);
    const uint32_t bs_u = (uint32_t)__cvta_generic_to_shared(Bs);

    const int lrowA = (lane & 7) + ((lane >> 3) & 1) * 8;
    const int lcolA = ((lane >> 4) & 1) * 8;
    const int lrowB = (lane & 7) + ((lane >> 4) & 1) * 8;
    const int lcolB = ((lane >> 3) & 1) * 8;

    float acc[4][8][4];
    #pragma unroll
    for (int i = 0; i < 4; i++)
        #pragma unroll
        for (int j = 0; j < 8; j++)
            #pragma unroll
            for (int r = 0; r < 4; r++) acc[i][j][r] = 0.f;

    const int nch = K / 32;

    #define GB_LOAD(cc, st) do {                                               \
        const int _k0 = (cc) * 32;                                             \
        _Pragma("unroll")                                                      \
        for (int _i = 0; _i < 4; _i++) {                                       \
            int _f = tid + _i * 128;                                           \
            int _r = _f >> 2, _s = (_f & 3) * 8;                               \
            cpasync16(as_u + (uint32_t)((st) * GSTGB + _r * GST + _s) * 2,     \
                      A + (size_t)(m0 + _r) * K + _k0 + _s,                    \
                      (m0 + _r < M) ? 16 : 0);                                 \
            cpasync16(bs_u + (uint32_t)((st) * GSTGB + _r * GST + _s) * 2,     \
                      B + (size_t)(n0 + _r) * K + _k0 + _s, 16);               \
        }                                                                      \
        cp_commit(); } while (0)

    GB_LOAD(0, 0);
    GB_LOAD(1, 1);   // nch >= 2 at every call site

    int st_c = 0, st_p = 2;
    for (int c = 0; c < nch; ++c) {
        if (c + 1 < nch) cp_wait1(); else cp_wait0();
        __syncthreads();

        if (c + 2 < nch) {
            GB_LOAD(c + 2, st_p);
        }

        const uint32_t a_base = as_u + (uint32_t)(st_c * GSTGB) * 2;
        const uint32_t b_base = bs_u + (uint32_t)(st_c * GSTGB) * 2;

        #pragma unroll
        for (int kk = 0; kk < 2; ++kk) {
            const int kb = kk * 16;
            uint32_t afr[4][4], bfr[8][2];
            #pragma unroll
            for (int mi = 0; mi < 4; mi++) {
                int m = wm * 64 + mi * 16;
                uint32_t addr = a_base + (uint32_t)((m + lrowA) * GST + kb + lcolA) * 2;
                LDSM_X4(afr[mi][0], afr[mi][1], afr[mi][2], afr[mi][3], addr);
            }
            #pragma unroll
            for (int njp = 0; njp < 4; njp++) {
                int n = wn * 64 + njp * 16;
                uint32_t addr = b_base + (uint32_t)((n + lrowB) * GST + kb + lcolB) * 2;
                LDSM_X4(bfr[njp * 2][0], bfr[njp * 2][1],
                        bfr[njp * 2 + 1][0], bfr[njp * 2 + 1][1], addr);
            }
            #pragma unroll
            for (int mi = 0; mi < 4; mi++)
                #pragma unroll
                for (int nj = 0; nj < 8; nj++)
                    MMA_F16(acc[mi][nj], afr[mi], bfr[nj]);
        }
        st_c = (st_c == 2) ? 0 : st_c + 1;
        st_p = (st_p == 2) ? 0 : st_p + 1;
    }

    #pragma unroll
    for (int mi = 0; mi < 4; mi++) {
        int r0 = m0 + wm * 64 + mi * 16 + g;
        #pragma unroll
        for (int nj = 0; nj < 8; nj++) {
            int cb = n0 + wn * 64 + nj * 8 + 2 * t;
            #pragma unroll
            for (int half_ = 0; half_ < 2; half_++) {
                int gm = r0 + half_ * 8;
                if (gm >= M) continue;
                #pragma unroll
                for (int q = 0; q < 2; q++) {
                    int gn = cb + q;
                    if (gn >= N) continue;
                    float v = acc[mi][nj][half_ * 2 + q];
                    if (EPI == 1 || EPI == 2 || EPI == 3) v += bias[gn];
                    if (EPI == 2)
                        v = 0.5f * v * (1.0f + erff(v * 0.70710678118654752f));
                    if (EPI == 3)
                        Cf[(size_t)gm * ldc + gn] = v + res[(size_t)gm * ldc + gn];
                    else
                        Ch[(size_t)gm * ldc + gn] = __float2half_rn(v);
                }
            }
        }
    }
}

// ---------------- QK^T fp16 mma per (b,h) ----------------------------------
__global__ void __launch_bounds__(256) qk_f16(const __half* __restrict__ qkv,
                                              __half* __restrict__ S)
{
    __shared__ __half Qs[128 * 72];
    __shared__ __half Ks[128 * 72];
    const int z = blockIdx.z, b = z / HEADS, h = z % HEADS;
    const __half* qb = qkv + (size_t)b * SEQ * EMB3 + h * HD;
    const __half* kb = qb + EMB;
    const int m0 = blockIdx.y * 128, n0 = blockIdx.x * 128;
    const int tid = threadIdx.x;
    const int warp = tid >> 5, lane = tid & 31;
    const int wm = warp >> 2, wn = warp & 3;
    const int g = lane >> 2, t = lane & 3;
    const uint32_t qs_u = (uint32_t)__cvta_generic_to_shared(Qs);
    const uint32_t ks_u = (uint32_t)__cvta_generic_to_shared(Ks);

    #pragma unroll
    for (int i = 0; i < 4; i++) {
        int s = tid + i * 256;
        int r = s >> 3, sg = (s & 7) * 8;
        cpasync16(qs_u + (size_t)(r * 72 + sg) * 2,
                  qb + (size_t)(m0 + r) * EMB3 + sg, (m0 + r < SEQ) ? 16 : 0);
        cpasync16(ks_u + (size_t)(r * 72 + sg) * 2,
                  kb + (size_t)(n0 + r) * EMB3 + sg, (n0 + r < SEQ) ? 16 : 0);
    }
    cp_commit(); cp_wait0();
    __syncthreads();

    float acc[4][4][4];
    #pragma unroll
    for (int i = 0; i < 4; i++)
        #pragma unroll
        for (int j = 0; j < 4; j++)
            #pragma unroll
            for (int r = 0; r < 4; r++) acc[i][j][r] = 0.f;

    const uint32_t* qs32 = (const uint32_t*)Qs;
    const uint32_t* ks32 = (const uint32_t*)Ks;
    #pragma unroll
    for (int kk = 0; kk < 4; ++kk) {
        const int kb2 = kk * 8;
        uint32_t afr[4][4], bfr[4][2];
        #pragma unroll
        for (int mi = 0; mi < 4; mi++) {
            int m = wm * 64 + mi * 16 + g;
            afr[mi][0] = qs32[(m    ) * 36 + kb2 + t];
            afr[mi][1] = qs32[(m + 8) * 36 + kb2 + t];
            afr[mi][2] = qs32[(m    ) * 36 + kb2 + t + 4];
            afr[mi][3] = qs32[(m + 8) * 36 + kb2 + t + 4];
        }
        #pragma unroll
        for (int nj = 0; nj < 4; nj++) {
            int n = wn * 32 + nj * 8 + g;
            bfr[nj][0] = ks32[n * 36 + kb2 + t];
            bfr[nj][1] = ks32[n * 36 + kb2 + t + 4];
        }
        #pragma unroll
        for (int mi = 0; mi < 4; mi++)
            #pragma unroll
            for (int nj = 0; nj < 4; nj++)
                MMA_F16(acc[mi][nj], afr[mi], bfr[nj]);
    }

    __half* Sz = S + (size_t)z * SEQ * SPAD;
    #pragma unroll
    for (int mi = 0; mi < 4; mi++) {
        int r0 = m0 + wm * 64 + mi * 16 + g;
        #pragma unroll
        for (int nj = 0; nj < 4; nj++) {
            int cb = n0 + wn * 32 + nj * 8 + 2 * t;
            #pragma unroll
            for (int half_ = 0; half_ < 2; half_++) {
                int gm = r0 + half_ * 8;
                if (gm >= SEQ) continue;
                #pragma unroll
                for (int q = 0; q < 2; q++) {
                    int gn = cb + q;
                    if (gn >= SEQ) continue;
                    Sz[(size_t)gm * SPAD + gn] =
                        __float2half_rn(acc[mi][nj][half_ * 2 + q] * 0.125f);
                }
            }
        }
    }
}

// ---------------- fused LN(KW) + softmax(KW) -------------------------------
__global__ void ln_softmax(__half* __restrict__ A, const float* __restrict__ g,
                           const float* __restrict__ bb)
{
    int warp = (blockIdx.x * blockDim.x + threadIdx.x) >> 5;
    int lane = threadIdx.x & 31;
    if (warp >= ROWSA) return;
    __half* row = A + (size_t)warp * SPAD;
    float v[7];
    float s = 0.f, ss = 0.f;
    #pragma unroll
    for (int i = 0; i < 7; i++) {
        int idx = lane + i * 32;
        v[i] = (idx < KW) ? __half2float(row[idx]) : 0.f;
        s += v[i]; ss += v[i] * v[i];
    }
    #pragma unroll
    for (int o = 16; o; o >>= 1) {
        s  += __shfl_xor_sync(0xffffffffu, s,  o);
        ss += __shfl_xor_sync(0xffffffffu, ss, o);
    }
    float mu  = s * (1.0f / KW);
    float var = ss * (1.0f / KW) - mu * mu;
    float inv = rsqrtf(var + 1e-5f);
    float mx = -1e30f;
    #pragma unroll
    for (int i = 0; i < 7; i++) {
        int idx = lane + i * 32;
        if (idx < KW) {
            float zv = (v[i] - mu) * inv * g[idx] + bb[idx];
            v[i] = zv;
            mx = fmaxf(mx, zv);
        } else v[i] = -1e30f;
    }
    #pragma unroll
    for (int o = 16; o; o >>= 1) mx = fmaxf(mx, __shfl_xor_sync(0xffffffffu, mx, o));
    float se = 0.f;
    #pragma unroll
    for (int i = 0; i < 7; i++) {
        int idx = lane + i * 32;
        float e = (idx < KW) ? __expf(v[i] - mx) : 0.f;
        v[i] = e; se += e;
    }
    #pragma unroll
    for (int o = 16; o; o >>= 1) se += __shfl_xor_sync(0xffffffffu, se, o);
    float r = 1.0f / se;
    #pragma unroll
    for (int i = 0; i < 7; i++) {
        int idx = lane + i * 32;
        if (idx < KW) row[idx] = __float2half_rn(v[i] * r);
    }
}

// ---------------- P^T V fp16 ------------------------------------------------
__global__ void __launch_bounds__(256) pv_f16(const __half* __restrict__ A,
                                              const __half* __restrict__ qkv,
                                              __half* __restrict__ y)
{
    __shared__ __half Ps[16 * 136];
    __shared__ __half Vs[16 * 72];
    const int z = blockIdx.y, b = z / HEADS, h = z % HEADS;
    const __half* Ab = A + (size_t)z * SEQ * SPAD;
    const __half* Vb = qkv + (size_t)b * SEQ * EMB3 + h * HD + 2 * EMB;
    const int m0 = blockIdx.x * 128;
    const int tid = threadIdx.x;
    const int warp = tid >> 5, lane = tid & 31;
    const int wm = warp >> 1, wn = warp & 1;
    const int g = lane >> 2, t = lane & 3;
    const uint32_t ps_u = (uint32_t)__cvta_generic_to_shared(Ps);
    const uint32_t vs_u = (uint32_t)__cvta_generic_to_shared(Vs);

    const int arow = (lane & 7) + ((lane >> 4) << 3);
    const int acol8 = ((lane >> 3) & 1) << 3;
    const int brow = (lane & 7) + (((lane >> 3) & 1) << 3);
    const int bcol8 = (lane >> 4) << 3;

    float acc[2][4][4];
    #pragma unroll
    for (int i = 0; i < 2; i++)
        #pragma unroll
        for (int j = 0; j < 4; j++)
            #pragma unroll
            for (int r = 0; r < 4; r++) acc[i][j][r] = 0.f;

    for (int c = 0; c < KWPAD / 16; ++c) {
        const int k0 = c * 16;
        {
            int r = tid >> 4, sg = (tid & 15) * 8;
            cpasync16(ps_u + (size_t)(r * 136 + sg) * 2,
                      Ab + (size_t)(k0 + r) * SPAD + m0 + sg,
                      (k0 + r < SEQ && m0 + sg < SPAD) ? 16 : 0);
        }
        if (tid < 128) {
            int r = tid >> 3, sg = (tid & 7) * 8;
            cpasync16(vs_u + (size_t)(r * 72 + sg) * 2,
                      Vb + (size_t)(k0 + r) * EMB3 + sg, (k0 + r < SEQ) ? 16 : 0);
        }
        cp_commit(); cp_wait0();
        __syncthreads();

        uint32_t afr[2][4], bfr[4][2];
        #pragma unroll
        for (int mi = 0; mi < 2; mi++) {
            uint32_t addr = ps_u + (size_t)(arow * 136 + wm * 32 + mi * 16 + acol8) * 2;
            LDSM_X4_T(afr[mi][0], afr[mi][1], afr[mi][2], afr[mi][3], addr);
        }
        #pragma unroll
        for (int njp = 0; njp < 2; njp++) {
            uint32_t addr = vs_u + (size_t)(brow * 72 + wn * 32 + njp * 16 + bcol8) * 2;
            LDSM_X4_T(bfr[njp * 2][0], bfr[njp * 2][1],
                      bfr[njp * 2 + 1][0], bfr[njp * 2 + 1][1], addr);
        }
        #pragma unroll
        for (int mi = 0; mi < 2; mi++)
            #pragma unroll
            for (int nj = 0; nj < 4; nj++)
                MMA_F16(acc[mi][nj], afr[mi], bfr[nj]);
        __syncthreads();
    }

    __half* yz = y + (size_t)z * KW * HD;
    #pragma unroll
    for (int mi = 0; mi < 2; mi++) {
        int r0 = m0 + wm * 32 + mi * 16 + g;
        #pragma unroll
        for (int nj = 0; nj < 4; nj++) {
            int cb = wn * 32 + nj * 8 + 2 * t;
            #pragma unroll
            for (int half_ = 0; half_ < 2; half_++) {
                int gm = r0 + half_ * 8;
                if (gm >= KW) continue;
                #pragma unroll
                for (int q = 0; q < 2; q++)
                    yz[(size_t)gm * HD + cb + q] =
                        __float2half_rn(acc[mi][nj][half_ * 2 + q]);
            }
        }
    }
}

// --------- fc2: x1 += Wt @ y + bias ----------------------------------------
__global__ void __launch_bounds__(256) out_f16(const __half* __restrict__ Wt,
                                               const __half* __restrict__ y,
                                               const float* __restrict__ bias,
                                               float* __restrict__ x1)
{
    __shared__ __half As[128 * 24];
    __shared__ __half Ys[16 * 72];
    const int z = blockIdx.y, b = z / HEADS, h = z % HEADS;
    const __half* yb = y + (size_t)z * KW * HD;
    const int m0 = blockIdx.x * 128;
    const int tid = threadIdx.x;
    const int warp = tid >> 5, lane = tid & 31;
    const int wm = warp >> 1, wn = warp & 1;
    const int g = lane >> 2, t = lane & 3;
    const uint32_t as_u = (uint32_t)__cvta_generic_to_shared(As);
    const uint32_t ys_u = (uint32_t)__cvta_generic_to_shared(Ys);

    const int brow = (lane & 7) + (((lane >> 3) & 1) << 3);
    const int bcol8 = (lane >> 4) << 3;

    float acc[2][4][4];
    #pragma unroll
    for (int i = 0; i < 2; i++)
        #pragma unroll
        for (int j = 0; j < 4; j++)
            #pragma unroll
            for (int r = 0; r < 4; r++) acc[i][j][r] = 0.f;

    for (int c = 0; c < KWPAD / 16; ++c) {
        const int k0 = c * 16;
        {
            int r = tid >> 1, sg = (tid & 1) * 8;
            cpasync16(as_u + (size_t)(r * 24 + sg) * 2,
                      Wt + (size_t)(m0 + r) * KWPAD + k0 + sg, 16);
        }
        if (tid < 128) {
            int r = tid >> 3, sg = (tid & 7) * 8;
            cpasync16(ys_u + (size_t)(r * 72 + sg) * 2,
                      yb + (size_t)(k0 + r) * HD + sg, (k0 + r < KW) ? 16 : 0);
        }
        cp_commit(); cp_wait0();
        __syncthreads();

        const uint32_t* as32 = (const uint32_t*)As;
        uint32_t afr[2][4], bfr[4][2];
        #pragma unroll
        for (int mi = 0; mi < 2; mi++) {
            int m = wm * 32 + mi * 16 + g;
            afr[mi][0] = as32[(m    ) * 12 + t];
            afr[mi][1] = as32[(m + 8) * 12 + t];
            afr[mi][2] = as32[(m    ) * 12 + t + 4];
            afr[mi][3] = as32[(m + 8) * 12 + t + 4];
        }
        #pragma unroll
        for (int njp = 0; njp < 2; njp++) {
            uint32_t addr = ys_u + (size_t)(brow * 72 + wn * 32 + njp * 16 + bcol8) * 2;
            LDSM_X4_T(bfr[njp * 2][0], bfr[njp * 2][1],
                      bfr[njp * 2 + 1][0], bfr[njp * 2 + 1][1], addr);
        }
        #pragma unroll
        for (int mi = 0; mi < 2; mi++)
            #pragma unroll
            for (int nj = 0; nj < 4; nj++)
                MMA_F16(acc[mi][nj], afr[mi], bfr[nj]);
        __syncthreads();
    }

    #pragma unroll
    for (int mi = 0; mi < 2; mi++) {
        int r0 = m0 + wm * 32 + mi * 16 + g;
        #pragma unroll
        for (int nj = 0; nj < 4; nj++) {
            int cb = wn * 32 + nj * 8 + 2 * t;
            #pragma unroll
            for (int half_ = 0; half_ < 2; half_++) {
                int gm = r0 + half_ * 8;
                if (gm >= SEQ) continue;
                float bv = bias[gm];
                #pragma unroll
                for (int q = 0; q < 2; q++) {
                    size_t idx = ((size_t)(b * SEQ + gm)) * EMB + h * HD + cb + q;
                    x1[idx] += acc[mi][nj][half_ * 2 + q] + bv;
                }
            }
        }
    }
}

// ---------------- launch ----------------
extern "C" void kernel_launch(void* const* d_in, const int* in_sizes, int n_in,
                              void* d_out, int out_size) {
    (void)in_sizes; (void)n_in; (void)out_size;
    const float* x         = (const float*)d_in[0];
    const float* qkv_w     = (const float*)d_in[1];
    const float* fc_w      = (const float*)d_in[2];
    const float* fc_b      = (const float*)d_in[3];
    const float* attn_ln_g = (const float*)d_in[4];
    const float* attn_ln_b = (const float*)d_in[5];
    const float* fc2_w     = (const float*)d_in[6];
    const float* fc2_b     = (const float*)d_in[7];
    const float* mlp_w1    = (const float*)d_in[8];
    const float* mlp_b1    = (const float*)d_in[9];
    const float* mlp_w2    = (const float*)d_in[10];
    const float* mlp_b2    = (const float*)d_in[11];
    const float* f_ln_g    = (const float*)d_in[12];
    const float* f_ln_b    = (const float*)d_in[13];
    const float* gl_ln_g   = (const float*)d_in[14];
    const float* gl_ln_b   = (const float*)d_in[15];

    float *px1, *px2;
    __half *pxn, *pqkv, *pS, *pA, *py, *ph;
    __half *pwqkv, *pwfc, *pw1, *pw2, *pwfc2t;
    cudaGetSymbolAddress((void**)&px1,  g_x1);
    cudaGetSymbolAddress((void**)&px2,  g_x2);
    cudaGetSymbolAddress((void**)&pxn,  g_xn);
    cudaGetSymbolAddress((void**)&pqkv, g_qkv);
    cudaGetSymbolAddress((void**)&pS,   g_S);
    cudaGetSymbolAddress((void**)&pA,   g_A);
    cudaGetSymbolAddress((void**)&py,   g_y);
    cudaGetSymbolAddress((void**)&ph,   g_h);
    cudaGetSymbolAddress((void**)&pwqkv,  g_wqkv);
    cudaGetSymbolAddress((void**)&pwfc,   g_wfc);
    cudaGetSymbolAddress((void**)&pw1,    g_w1);
    cudaGetSymbolAddress((void**)&pw2,    g_w2);
    cudaGetSymbolAddress((void**)&pwfc2t, g_wfc2t);

    cudaFuncSetAttribute(gemm_big<1>, cudaFuncAttributeMaxDynamicSharedMemorySize, GB_SMEM);
    cudaFuncSetAttribute(gemm_big<2>, cudaFuncAttributeMaxDynamicSharedMemorySize, GB_SMEM);
    cudaFuncSetAttribute(gemm_big<3>, cudaFuncAttributeMaxDynamicSharedMemorySize, GB_SMEM);
    cudaFuncSetAttribute(gemm_big<4>, cudaFuncAttributeMaxDynamicSharedMemorySize, GB_SMEM);

    const int NE = TOK * EMB;

    prep_wT<<<CDIV(EMB*EMB3, 256), 256>>>(qkv_w, pwqkv, EMB, EMB3);
    prep_wT<<<CDIV(EMB*HIDDEN, 256), 256>>>(mlp_w1, pw1, EMB, HIDDEN);
    prep_wT<<<CDIV(HIDDEN*EMB, 256), 256>>>(mlp_w2, pw2, HIDDEN, EMB);
    prep_fcT<<<CDIV(256*SPAD, 256), 256>>>(fc_w, pwfc);
    prep_fc2T<<<CDIV(256*KWPAD, 256), 256>>>(fc2_w, pwfc2t);
    zero_pad_S<<<CDIV(ROWSA*(SPAD-KW), 256), 256>>>(pS);

    init_copy<<<CDIV(NE, 256), 256>>>(x, px1, px2, NE);

    for (int l = 0; l < NLAYERS; ++l) {
        // y1 = x1 + attention(LN_f(x2))
        ln_row768<<<TOK, 256>>>(px2, f_ln_g + l * EMB, f_ln_b + l * EMB, pxn);
        gemm_big<4><<<dim3(EMB3/128, CDIV(TOK,128)), 128, GB_SMEM>>>(
            pxn, pwqkv, nullptr, nullptr, pqkv, nullptr, EMB3, TOK, EMB3, EMB);
        qk_f16<<<dim3(2, 2, BH), 256>>>(pqkv, pS);
        gemm_big<1><<<dim3(CDIV(KW,128), CDIV(ROWSA,128)), 128, GB_SMEM>>>(
            pS, pwfc, fc_b, nullptr, pA, nullptr, SPAD, ROWSA, KW, SPAD);
        ln_softmax<<<ROWSA / 8, 256>>>(pA, attn_ln_g, attn_ln_b);
        pv_f16<<<dim3(2, BH), 256>>>(pA, pqkv, py);
        out_f16<<<dim3(2, BH), 256>>>(pwfc2t, py, fc2_b, px1);
        // y2 = x2 + mlp(LN_g(y1))
        ln_row768<<<TOK, 256>>>(px1, gl_ln_g + l * EMB, gl_ln_b + l * EMB, pxn);
        gemm_big<2><<<dim3(HIDDEN/128, CDIV(TOK,128)), 128, GB_SMEM>>>(
            pxn, pw1, mlp_b1, nullptr, ph, nullptr, HIDDEN, TOK, HIDDEN, EMB);
        gemm_big<3><<<dim3(EMB/128, CDIV(TOK,128)), 128, GB_SMEM>>>(
            ph, pw2, mlp_b2, px2, nullptr, px2, EMB, TOK, EMB, HIDDEN);
    }

    finalize_k<<<CDIV(NE, 256), 256>>>(px1, px2, (float*)d_out, NE);
}

// round 13
// speedup vs baseline: 1.0834x; 1.0834x over previous
#include <cuda_runtime.h>
#include <cuda_fp16.h>
#include <math.h>
#include <stdint.h>

#define BATCH   32
#define SEQ     197
#define EMB     768
#define EMB3    2304
#define HEADS   12
#define HD      64
#define KW      197
#define NLAYERS 12
#define HIDDEN  3072
#define TOK     (BATCH*SEQ)       // 6304
#define BH      (BATCH*HEADS)     // 384
#define ROWSA   (BH*SEQ)          // 75648
#define SPAD    224
#define KWPAD   208

#define CDIV(a,b) (((a)+(b)-1)/(b))

// ---------------- scratch ----------------
static __device__ float  g_x1 [TOK*EMB];
static __device__ float  g_x2 [TOK*EMB];
static __device__ __half g_xn [TOK*EMB];
static __device__ __half g_qkv[TOK*EMB3];
static __device__ __half g_A  [(size_t)BH*SEQ*SPAD];
static __device__ __half g_G  [(size_t)BH*SPAD*HD];
static __device__ __half g_y  [BH*KW*HD];
static __device__ __half g_h  [TOK*HIDDEN];
static __device__ __half g_wqkv [EMB3*EMB];
static __device__ __half g_wfcp [SPAD*SPAD];      // fc_w zero-padded [m][j]
static __device__ __half g_w1   [HIDDEN*EMB];
static __device__ __half g_w2   [EMB*HIDDEN];
static __device__ __half g_wfc2t[256*KWPAD];

// ---------------- helpers ----------------
__device__ __forceinline__ void cpasync16(uint32_t dst, const void* src, int srcbytes) {
    asm volatile("cp.async.cg.shared.global [%0], [%1], 16, %2;\n"
                 :: "r"(dst), "l"(src), "r"(srcbytes));
}
__device__ __forceinline__ void cp_commit() { asm volatile("cp.async.commit_group;\n"); }
__device__ __forceinline__ void cp_wait0() { asm volatile("cp.async.wait_group 0;\n"); }
__device__ __forceinline__ void cp_wait1() { asm volatile("cp.async.wait_group 1;\n"); }

#define MMA_F16(acc, afr, bfr)                                               \
    asm volatile(                                                            \
        "mma.sync.aligned.m16n8k16.row.col.f32.f16.f16.f32 "                 \
        "{%0,%1,%2,%3}, {%4,%5,%6,%7}, {%8,%9}, {%0,%1,%2,%3};\n"            \
        : "+f"((acc)[0]), "+f"((acc)[1]), "+f"((acc)[2]), "+f"((acc)[3])     \
        : "r"((afr)[0]), "r"((afr)[1]), "r"((afr)[2]), "r"((afr)[3]),        \
          "r"((bfr)[0]), "r"((bfr)[1]))

#define LDSM_X4(r0, r1, r2, r3, addr)                                        \
    asm volatile("ldmatrix.sync.aligned.m8n8.x4.shared.b16 "                 \
                 "{%0,%1,%2,%3}, [%4];"                                      \
                 : "=r"(r0), "=r"(r1), "=r"(r2), "=r"(r3) : "r"(addr))

#define LDSM_X4_T(r0, r1, r2, r3, addr)                                      \
    asm volatile("ldmatrix.sync.aligned.m8n8.x4.trans.shared.b16 "           \
                 "{%0,%1,%2,%3}, [%4];"                                      \
                 : "=r"(r0), "=r"(r1), "=r"(r2), "=r"(r3) : "r"(addr))

// ---------------- elementwise / prep ----------------
__global__ void init_copy(const float* __restrict__ x, float* __restrict__ x1,
                          float* __restrict__ x2, int n) {
    int i = blockIdx.x * blockDim.x + threadIdx.x;
    if (i < n) { float v = x[i]; x1[i] = v; x2[i] = v; }
}

__global__ void finalize_k(const float* __restrict__ x1, const float* __restrict__ x2,
                           float* __restrict__ out, int n) {
    int i = blockIdx.x * blockDim.x + threadIdx.x;
    if (i < n) out[i] = 0.5f * (x1[i] + x2[i]);
}

__global__ void prep_wT(const float* __restrict__ s, __half* __restrict__ d,
                        int K, int N) {
    int i = blockIdx.x * blockDim.x + threadIdx.x;
    if (i < N * K) {
        int n = i / K, k = i % K;
        d[i] = __float2half_rn(s[(size_t)k * N + n]);
    }
}

// fc_w (SEQ,KW) -> padded [SPAD][SPAD] half, original orientation [m][j]
__global__ void prep_fcpad(const float* __restrict__ s, __half* __restrict__ d) {
    int i = blockIdx.x * blockDim.x + threadIdx.x;
    if (i < SPAD * SPAD) {
        int m = i / SPAD, j = i % SPAD;
        d[i] = (m < SEQ && j < KW) ? __float2half_rn(s[m * KW + j]) : __float2half(0.f);
    }
}

// fc2_w (KW,SEQ) -> Wt[256][KWPAD]: Wt[n2][k=kw]
__global__ void prep_fc2T(const float* __restrict__ s, __half* __restrict__ d) {
    int i = blockIdx.x * blockDim.x + threadIdx.x;
    if (i < 256 * KWPAD) {
        int n2 = i / KWPAD, k = i % KWPAD;
        d[i] = (n2 < SEQ && k < KW) ? __float2half_rn(s[k * SEQ + n2]) : __float2half(0.f);
    }
}

// ---------------- layernorm rows of 768 -> half ----------------
__global__ void ln_row768(const float* __restrict__ x, const float* __restrict__ g,
                          const float* __restrict__ b, __half* __restrict__ out) {
    int row = blockIdx.x;
    const float* xr = x + (size_t)row * EMB;
    __half* orow = out + (size_t)row * EMB;
    int tid = threadIdx.x;
    float s = 0.f, ss = 0.f;
    for (int i = tid; i < EMB; i += 256) { float v = xr[i]; s += v; ss += v * v; }
    __shared__ float rs[8], rss[8];
    #pragma unroll
    for (int o = 16; o; o >>= 1) {
        s  += __shfl_xor_sync(0xffffffffu, s,  o);
        ss += __shfl_xor_sync(0xffffffffu, ss, o);
    }
    if ((tid & 31) == 0) { rs[tid >> 5] = s; rss[tid >> 5] = ss; }
    __syncthreads();
    if (tid < 32) {
        float a = (tid < 8) ? rs[tid]  : 0.f;
        float c = (tid < 8) ? rss[tid] : 0.f;
        #pragma unroll
        for (int o = 4; o; o >>= 1) {
            a += __shfl_xor_sync(0xffffffffu, a, o);
            c += __shfl_xor_sync(0xffffffffu, c, o);
        }
        if (tid == 0) { rs[0] = a; rss[0] = c; }
    }
    __syncthreads();
    float mu  = rs[0] * (1.0f / EMB);
    float var = rss[0] * (1.0f / EMB) - mu * mu;
    float inv = rsqrtf(var + 1e-5f);
    for (int i = tid; i < EMB; i += 256)
        orow[i] = __float2half_rn((xr[i] - mu) * inv * g[i] + b[i]);
}

// ================= fp16 GEMM (R7-proven): C = A[M,K] @ Bt[N,K]^T ===========
// 128x128x32 tiles, 3-stage cp.async pipeline, ldmatrix fragments.
// EPI: 1 +bias->half | 2 +bias,gelu->half | 3 +bias,+res->float | 4 ->half
#define GST 40
#define GSTG (128*GST)

template <int EPI>
__global__ void __launch_bounds__(256) gemm_f16(
    const __half* __restrict__ A, const __half* __restrict__ B,
    const float* __restrict__ bias, const float* __restrict__ res,
    __half* __restrict__ Ch, float* __restrict__ Cf,
    int ldc, int M, int N, int K)
{
    __shared__ __half As[3 * GSTG];
    __shared__ __half Bs[3 * GSTG];
    const int tid  = threadIdx.x;
    const int warp = tid >> 5, lane = tid & 31;
    const int wm = warp >> 2, wn = warp & 3;
    const int g = lane >> 2, t = lane & 3;
    const int m0 = blockIdx.y * 128, n0 = blockIdx.x * 128;

    const uint32_t as_u = (uint32_t)__cvta_generic_to_shared(As);
    const uint32_t bs_u = (uint32_t)__cvta_generic_to_shared(Bs);

    const int r0i = tid >> 2, seg = (tid & 3) * 8;
    const int r1i = (tid + 256) >> 2;

    const int lrowA = (lane & 7) + ((lane >> 3) & 1) * 8;
    const int lcolA = ((lane >> 4) & 1) * 8;
    const int lrowB = (lane & 7) + ((lane >> 4) & 1) * 8;
    const int lcolB = ((lane >> 3) & 1) * 8;

    float acc[4][4][4];
    #pragma unroll
    for (int i = 0; i < 4; i++)
        #pragma unroll
        for (int j = 0; j < 4; j++)
            #pragma unroll
            for (int r = 0; r < 4; r++) acc[i][j][r] = 0.f;

    const int nch = K / 32;

    #pragma unroll
    for (int p = 0; p < 2; p++) {
        const int k0 = p * 32;
        const int so = p * GSTG;
        cpasync16(as_u + (uint32_t)(so + r0i * GST + seg) * 2,
                  A + (size_t)(m0 + r0i) * K + k0 + seg, (m0 + r0i < M) ? 16 : 0);
        cpasync16(as_u + (uint32_t)(so + r1i * GST + seg) * 2,
                  A + (size_t)(m0 + r1i) * K + k0 + seg, (m0 + r1i < M) ? 16 : 0);
        cpasync16(bs_u + (uint32_t)(so + r0i * GST + seg) * 2,
                  B + (size_t)(n0 + r0i) * K + k0 + seg, 16);
        cpasync16(bs_u + (uint32_t)(so + r1i * GST + seg) * 2,
                  B + (size_t)(n0 + r1i) * K + k0 + seg, 16);
        cp_commit();
    }

    int st_c = 0, st_p = 2;
    for (int c = 0; c < nch; ++c) {
        if (c + 1 < nch) cp_wait1(); else cp_wait0();
        __syncthreads();

        if (c + 2 < nch) {
            const int k0 = (c + 2) * 32;
            const int so = st_p * GSTG;
            cpasync16(as_u + (uint32_t)(so + r0i * GST + seg) * 2,
                      A + (size_t)(m0 + r0i) * K + k0 + seg, (m0 + r0i < M) ? 16 : 0);
            cpasync16(as_u + (uint32_t)(so + r1i * GST + seg) * 2,
                      A + (size_t)(m0 + r1i) * K + k0 + seg, (m0 + r1i < M) ? 16 : 0);
            cpasync16(bs_u + (uint32_t)(so + r0i * GST + seg) * 2,
                      B + (size_t)(n0 + r0i) * K + k0 + seg, 16);
            cpasync16(bs_u + (uint32_t)(so + r1i * GST + seg) * 2,
                      B + (size_t)(n0 + r1i) * K + k0 + seg, 16);
            cp_commit();
        }

        const uint32_t a_base = as_u + (uint32_t)(st_c * GSTG) * 2;
        const uint32_t b_base = bs_u + (uint32_t)(st_c * GSTG) * 2;

        #pragma unroll
        for (int kk = 0; kk < 2; ++kk) {
            const int kb = kk * 16;
            uint32_t afr[4][4], bfr[4][2];
            #pragma unroll
            for (int mi = 0; mi < 4; mi++) {
                int m = wm * 64 + mi * 16;
                uint32_t addr = a_base + (uint32_t)((m + lrowA) * GST + kb + lcolA) * 2;
                LDSM_X4(afr[mi][0], afr[mi][1], afr[mi][2], afr[mi][3], addr);
            }
            #pragma unroll
            for (int njp = 0; njp < 2; njp++) {
                int n = wn * 32 + njp * 16;
                uint32_t addr = b_base + (uint32_t)((n + lrowB) * GST + kb + lcolB) * 2;
                LDSM_X4(bfr[njp * 2][0], bfr[njp * 2][1],
                        bfr[njp * 2 + 1][0], bfr[njp * 2 + 1][1], addr);
            }
            #pragma unroll
            for (int mi = 0; mi < 4; mi++)
                #pragma unroll
                for (int nj = 0; nj < 4; nj++)
                    MMA_F16(acc[mi][nj], afr[mi], bfr[nj]);
        }
        st_c = (st_c == 2) ? 0 : st_c + 1;
        st_p = (st_p == 2) ? 0 : st_p + 1;
    }

    #pragma unroll
    for (int mi = 0; mi < 4; mi++) {
        int r0 = m0 + wm * 64 + mi * 16 + g;
        #pragma unroll
        for (int nj = 0; nj < 4; nj++) {
            int cb = n0 + wn * 32 + nj * 8 + 2 * t;
            #pragma unroll
            for (int half_ = 0; half_ < 2; half_++) {
                int gm = r0 + half_ * 8;
                if (gm >= M) continue;
                #pragma unroll
                for (int q = 0; q < 2; q++) {
                    int gn = cb + q;
                    if (gn >= N) continue;
                    float v = acc[mi][nj][half_ * 2 + q];
                    if (EPI == 1 || EPI == 2 || EPI == 3) v += bias[gn];
                    if (EPI == 2)
                        v = 0.5f * v * (1.0f + erff(v * 0.70710678118654752f));
                    if (EPI == 3)
                        Cf[(size_t)gm * ldc + gn] = v + res[(size_t)gm * ldc + gn];
                    else
                        Ch[(size_t)gm * ldc + gn] = __float2half_rn(v);
                }
            }
        }
    }
}

// ---------------- kg: Gt[z,j,d] = 0.125 * sum_m fc_w[m,j] K[m,d] -----------
// Structure = pv_f16 (transpose-on-load A, reduction over tokens m).
__global__ void __launch_bounds__(256) kg_f16(const __half* __restrict__ Wp,
                                              const __half* __restrict__ qkv,
                                              __half* __restrict__ G)
{
    __shared__ __half Ps[16 * 136];
    __shared__ __half Ks[16 * 72];
    const int z = blockIdx.y, b = z / HEADS, h = z % HEADS;
    const __half* Kb = qkv + (size_t)b * SEQ * EMB3 + h * HD + EMB;
    const int m0 = blockIdx.x * 128;   // j range
    const int tid = threadIdx.x;
    const int warp = tid >> 5, lane = tid & 31;
    const int wm = warp >> 1, wn = warp & 1;
    const int g = lane >> 2, t = lane & 3;
    const uint32_t ps_u = (uint32_t)__cvta_generic_to_shared(Ps);
    const uint32_t vs_u = (uint32_t)__cvta_generic_to_shared(Ks);

    const int arow = (lane & 7) + ((lane >> 4) << 3);
    const int acol8 = ((lane >> 3) & 1) << 3;
    const int brow = (lane & 7) + (((lane >> 3) & 1) << 3);
    const int bcol8 = (lane >> 4) << 3;

    float acc[2][4][4];
    #pragma unroll
    for (int i = 0; i < 2; i++)
        #pragma unroll
        for (int j = 0; j < 4; j++)
            #pragma unroll
            for (int r = 0; r < 4; r++) acc[i][j][r] = 0.f;

    for (int c = 0; c < KWPAD / 16; ++c) {
        const int k0 = c * 16;
        {
            int r = tid >> 4, sg = (tid & 15) * 8;
            cpasync16(ps_u + (size_t)(r * 136 + sg) * 2,
                      Wp + (size_t)(k0 + r) * SPAD + m0 + sg,
                      (k0 + r < SEQ && m0 + sg < SPAD) ? 16 : 0);
        }
        if (tid < 128) {
            int r = tid >> 3, sg = (tid & 7) * 8;
            cpasync16(vs_u + (size_t)(r * 72 + sg) * 2,
                      Kb + (size_t)(k0 + r) * EMB3 + sg, (k0 + r < SEQ) ? 16 : 0);
        }
        cp_commit(); cp_wait0();
        __syncthreads();

        uint32_t afr[2][4], bfr[4][2];
        #pragma unroll
        for (int mi = 0; mi < 2; mi++) {
            uint32_t addr = ps_u + (size_t)(arow * 136 + wm * 32 + mi * 16 + acol8) * 2;
            LDSM_X4_T(afr[mi][0], afr[mi][1], afr[mi][2], afr[mi][3], addr);
        }
        #pragma unroll
        for (int njp = 0; njp < 2; njp++) {
            uint32_t addr = vs_u + (size_t)(brow * 72 + wn * 32 + njp * 16 + bcol8) * 2;
            LDSM_X4_T(bfr[njp * 2][0], bfr[njp * 2][1],
                      bfr[njp * 2 + 1][0], bfr[njp * 2 + 1][1], addr);
        }
        #pragma unroll
        for (int mi = 0; mi < 2; mi++)
            #pragma unroll
            for (int nj = 0; nj < 4; nj++)
                MMA_F16(acc[mi][nj], afr[mi], bfr[nj]);
        __syncthreads();
    }

    __half* Gz = G + (size_t)z * SPAD * HD;
    #pragma unroll
    for (int mi = 0; mi < 2; mi++) {
        int r0 = m0 + wm * 32 + mi * 16 + g;
        #pragma unroll
        for (int nj = 0; nj < 4; nj++) {
            int cb = wn * 32 + nj * 8 + 2 * t;
            #pragma unroll
            for (int half_ = 0; half_ < 2; half_++) {
                int gm = r0 + half_ * 8;
                if (gm >= SPAD) continue;
                #pragma unroll
                for (int q = 0; q < 2; q++)
                    Gz[(size_t)gm * HD + cb + q] =
                        __float2half_rn(acc[mi][nj][half_ * 2 + q] * 0.125f);
            }
        }
    }
}

// ---------------- qg: A[z,n,j] = sum_d Q[n,d] Gt[j,d] + fc_b[j] ------------
// Structure = qk_f16 with B <- Gt.
__global__ void __launch_bounds__(256) qg_f16(const __half* __restrict__ qkv,
                                              const __half* __restrict__ G,
                                              const float* __restrict__ fc_b,
                                              __half* __restrict__ Aout)
{
    __shared__ __half Qs[128 * 72];
    __shared__ __half Ks[128 * 72];
    const int z = blockIdx.z, b = z / HEADS, h = z % HEADS;
    const __half* qb = qkv + (size_t)b * SEQ * EMB3 + h * HD;
    const __half* Gb = G + (size_t)z * SPAD * HD;
    const int m0 = blockIdx.y * 128, n0 = blockIdx.x * 128;
    const int tid = threadIdx.x;
    const int warp = tid >> 5, lane = tid & 31;
    const int wm = warp >> 2, wn = warp & 3;
    const int g = lane >> 2, t = lane & 3;
    const uint32_t qs_u = (uint32_t)__cvta_generic_to_shared(Qs);
    const uint32_t ks_u = (uint32_t)__cvta_generic_to_shared(Ks);

    #pragma unroll
    for (int i = 0; i < 4; i++) {
        int s = tid + i * 256;
        int r = s >> 3, sg = (s & 7) * 8;
        cpasync16(qs_u + (size_t)(r * 72 + sg) * 2,
                  qb + (size_t)(m0 + r) * EMB3 + sg, (m0 + r < SEQ) ? 16 : 0);
        cpasync16(ks_u + (size_t)(r * 72 + sg) * 2,
                  Gb + (size_t)(n0 + r) * HD + sg, (n0 + r < SPAD) ? 16 : 0);
    }
    cp_commit(); cp_wait0();
    __syncthreads();

    float acc[4][4][4];
    #pragma unroll
    for (int i = 0; i < 4; i++)
        #pragma unroll
        for (int j = 0; j < 4; j++)
            #pragma unroll
            for (int r = 0; r < 4; r++) acc[i][j][r] = 0.f;

    const uint32_t* qs32 = (const uint32_t*)Qs;
    const uint32_t* ks32 = (const uint32_t*)Ks;
    #pragma unroll
    for (int kk = 0; kk < 4; ++kk) {
        const int kb2 = kk * 8;
        uint32_t afr[4][4], bfr[4][2];
        #pragma unroll
        for (int mi = 0; mi < 4; mi++) {
            int m = wm * 64 + mi * 16 + g;
            afr[mi][0] = qs32[(m    ) * 36 + kb2 + t];
            afr[mi][1] = qs32[(m + 8) * 36 + kb2 + t];
            afr[mi][2] = qs32[(m    ) * 36 + kb2 + t + 4];
            afr[mi][3] = qs32[(m + 8) * 36 + kb2 + t + 4];
        }
        #pragma unroll
        for (int nj = 0; nj < 4; nj++) {
            int n = wn * 32 + nj * 8 + g;
            bfr[nj][0] = ks32[n * 36 + kb2 + t];
            bfr[nj][1] = ks32[n * 36 + kb2 + t + 4];
        }
        #pragma unroll
        for (int mi = 0; mi < 4; mi++)
            #pragma unroll
            for (int nj = 0; nj < 4; nj++)
                MMA_F16(acc[mi][nj], afr[mi], bfr[nj]);
    }

    __half* Az = Aout + (size_t)z * SEQ * SPAD;
    #pragma unroll
    for (int mi = 0; mi < 4; mi++) {
        int r0 = m0 + wm * 64 + mi * 16 + g;
        #pragma unroll
        for (int nj = 0; nj < 4; nj++) {
            int cb = n0 + wn * 32 + nj * 8 + 2 * t;
            #pragma unroll
            for (int half_ = 0; half_ < 2; half_++) {
                int gm = r0 + half_ * 8;
                if (gm >= SEQ) continue;
                #pragma unroll
                for (int q = 0; q < 2; q++) {
                    int gn = cb + q;
                    if (gn >= KW) continue;
                    Az[(size_t)gm * SPAD + gn] =
                        __float2half_rn(acc[mi][nj][half_ * 2 + q] + fc_b[gn]);
                }
            }
        }
    }
}

// ---------------- fused LN(KW) + softmax(KW) -------------------------------
__global__ void ln_softmax(__half* __restrict__ A, const float* __restrict__ g,
                           const float* __restrict__ bb)
{
    int warp = (blockIdx.x * blockDim.x + threadIdx.x) >> 5;
    int lane = threadIdx.x & 31;
    if (warp >= ROWSA) return;
    __half* row = A + (size_t)warp * SPAD;
    float v[7];
    float s = 0.f, ss = 0.f;
    #pragma unroll
    for (int i = 0; i < 7; i++) {
        int idx = lane + i * 32;
        v[i] = (idx < KW) ? __half2float(row[idx]) : 0.f;
        s += v[i]; ss += v[i] * v[i];
    }
    #pragma unroll
    for (int o = 16; o; o >>= 1) {
        s  += __shfl_xor_sync(0xffffffffu, s,  o);
        ss += __shfl_xor_sync(0xffffffffu, ss, o);
    }
    float mu  = s * (1.0f / KW);
    float var = ss * (1.0f / KW) - mu * mu;
    float inv = rsqrtf(var + 1e-5f);
    float mx = -1e30f;
    #pragma unroll
    for (int i = 0; i < 7; i++) {
        int idx = lane + i * 32;
        if (idx < KW) {
            float zv = (v[i] - mu) * inv * g[idx] + bb[idx];
            v[i] = zv;
            mx = fmaxf(mx, zv);
        } else v[i] = -1e30f;
    }
    #pragma unroll
    for (int o = 16; o; o >>= 1) mx = fmaxf(mx, __shfl_xor_sync(0xffffffffu, mx, o));
    float se = 0.f;
    #pragma unroll
    for (int i = 0; i < 7; i++) {
        int idx = lane + i * 32;
        float e = (idx < KW) ? __expf(v[i] - mx) : 0.f;
        v[i] = e; se += e;
    }
    #pragma unroll
    for (int o = 16; o; o >>= 1) se += __shfl_xor_sync(0xffffffffu, se, o);
    float r = 1.0f / se;
    #pragma unroll
    for (int i = 0; i < 7; i++) {
        int idx = lane + i * 32;
        if (idx < KW) row[idx] = __float2half_rn(v[i] * r);
    }
}

// ---------------- P^T V fp16 ------------------------------------------------
__global__ void __launch_bounds__(256) pv_f16(const __half* __restrict__ A,
                                              const __half* __restrict__ qkv,
                                              __half* __restrict__ y)
{
    __shared__ __half Ps[16 * 136];
    __shared__ __half Vs[16 * 72];
    const int z = blockIdx.y, b = z / HEADS, h = z % HEADS;
    const __half* Ab = A + (size_t)z * SEQ * SPAD;
    const __half* Vb = qkv + (size_t)b * SEQ * EMB3 + h * HD + 2 * EMB;
    const int m0 = blockIdx.x * 128;
    const int tid = threadIdx.x;
    const int warp = tid >> 5, lane = tid & 31;
    const int wm = warp >> 1, wn = warp & 1;
    const int g = lane >> 2, t = lane & 3;
    const uint32_t ps_u = (uint32_t)__cvta_generic_to_shared(Ps);
    const uint32_t vs_u = (uint32_t)__cvta_generic_to_shared(Vs);

    const int arow = (lane & 7) + ((lane >> 4) << 3);
    const int acol8 = ((lane >> 3) & 1) << 3;
    const int brow = (lane & 7) + (((lane >> 3) & 1) << 3);
    const int bcol8 = (lane >> 4) << 3;

    float acc[2][4][4];
    #pragma unroll
    for (int i = 0; i < 2; i++)
        #pragma unroll
        for (int j = 0; j < 4; j++)
            #pragma unroll
            for (int r = 0; r < 4; r++) acc[i][j][r] = 0.f;

    for (int c = 0; c < KWPAD / 16; ++c) {
        const int k0 = c * 16;
        {
            int r = tid >> 4, sg = (tid & 15) * 8;
            cpasync16(ps_u + (size_t)(r * 136 + sg) * 2,
                      Ab + (size_t)(k0 + r) * SPAD + m0 + sg,
                      (k0 + r < SEQ && m0 + sg < SPAD) ? 16 : 0);
        }
        if (tid < 128) {
            int r = tid >> 3, sg = (tid & 7) * 8;
            cpasync16(vs_u + (size_t)(r * 72 + sg) * 2,
                      Vb + (size_t)(k0 + r) * EMB3 + sg, (k0 + r < SEQ) ? 16 : 0);
        }
        cp_commit(); cp_wait0();
        __syncthreads();

        uint32_t afr[2][4], bfr[4][2];
        #pragma unroll
        for (int mi = 0; mi < 2; mi++) {
            uint32_t addr = ps_u + (size_t)(arow * 136 + wm * 32 + mi * 16 + acol8) * 2;
            LDSM_X4_T(afr[mi][0], afr[mi][1], afr[mi][2], afr[mi][3], addr);
        }
        #pragma unroll
        for (int njp = 0; njp < 2; njp++) {
            uint32_t addr = vs_u + (size_t)(brow * 72 + wn * 32 + njp * 16 + bcol8) * 2;
            LDSM_X4_T(bfr[njp * 2][0], bfr[njp * 2][1],
                      bfr[njp * 2 + 1][0], bfr[njp * 2 + 1][1], addr);
        }
        #pragma unroll
        for (int mi = 0; mi < 2; mi++)
            #pragma unroll
            for (int nj = 0; nj < 4; nj++)
                MMA_F16(acc[mi][nj], afr[mi], bfr[nj]);
        __syncthreads();
    }

    __half* yz = y + (size_t)z * KW * HD;
    #pragma unroll
    for (int mi = 0; mi < 2; mi++) {
        int r0 = m0 + wm * 32 + mi * 16 + g;
        #pragma unroll
        for (int nj = 0; nj < 4; nj++) {
            int cb = wn * 32 + nj * 8 + 2 * t;
            #pragma unroll
            for (int half_ = 0; half_ < 2; half_++) {
                int gm = r0 + half_ * 8;
                if (gm >= KW) continue;
                #pragma unroll
                for (int q = 0; q < 2; q++)
                    yz[(size_t)gm * HD + cb + q] =
                        __float2half_rn(acc[mi][nj][half_ * 2 + q]);
            }
        }
    }
}

// --------- fc2: x1 += Wt @ y + bias ----------------------------------------
__global__ void __launch_bounds__(256) out_f16(const __half* __restrict__ Wt,
                                               const __half* __restrict__ y,
                                               const float* __restrict__ bias,
                                               float* __restrict__ x1)
{
    __shared__ __half As[128 * 24];
    __shared__ __half Ys[16 * 72];
    const int z = blockIdx.y, b = z / HEADS, h = z % HEADS;
    const __half* yb = y + (size_t)z * KW * HD;
    const int m0 = blockIdx.x * 128;
    const int tid = threadIdx.x;
    const int warp = tid >> 5, lane = tid & 31;
    const int wm = warp >> 1, wn = warp & 1;
    const int g = lane >> 2, t = lane & 3;
    const uint32_t as_u = (uint32_t)__cvta_generic_to_shared(As);
    const uint32_t ys_u = (uint32_t)__cvta_generic_to_shared(Ys);

    const int brow = (lane & 7) + (((lane >> 3) & 1) << 3);
    const int bcol8 = (lane >> 4) << 3;

    float acc[2][4][4];
    #pragma unroll
    for (int i = 0; i < 2; i++)
        #pragma unroll
        for (int j = 0; j < 4; j++)
            #pragma unroll
            for (int r = 0; r < 4; r++) acc[i][j][r] = 0.f;

    for (int c = 0; c < KWPAD / 16; ++c) {
        const int k0 = c * 16;
        {
            int r = tid >> 1, sg = (tid & 1) * 8;
            cpasync16(as_u + (size_t)(r * 24 + sg) * 2,
                      Wt + (size_t)(m0 + r) * KWPAD + k0 + sg, 16);
        }
        if (tid < 128) {
            int r = tid >> 3, sg = (tid & 7) * 8;
            cpasync16(ys_u + (size_t)(r * 72 + sg) * 2,
                      yb + (size_t)(k0 + r) * HD + sg, (k0 + r < KW) ? 16 : 0);
        }
        cp_commit(); cp_wait0();
        __syncthreads();

        const uint32_t* as32 = (const uint32_t*)As;
        uint32_t afr[2][4], bfr[4][2];
        #pragma unroll
        for (int mi = 0; mi < 2; mi++) {
            int m = wm * 32 + mi * 16 + g;
            afr[mi][0] = as32[(m    ) * 12 + t];
            afr[mi][1] = as32[(m + 8) * 12 + t];
            afr[mi][2] = as32[(m    ) * 12 + t + 4];
            afr[mi][3] = as32[(m + 8) * 12 + t + 4];
        }
        #pragma unroll
        for (int njp = 0; njp < 2; njp++) {
            uint32_t addr = ys_u + (size_t)(brow * 72 + wn * 32 + njp * 16 + bcol8) * 2;
            LDSM_X4_T(bfr[njp * 2][0], bfr[njp * 2][1],
                      bfr[njp * 2 + 1][0], bfr[njp * 2 + 1][1], addr);
        }
        #pragma unroll
        for (int mi = 0; mi < 2; mi++)
            #pragma unroll
            for (int nj = 0; nj < 4; nj++)
                MMA_F16(acc[mi][nj], afr[mi], bfr[nj]);
        __syncthreads();
    }

    #pragma unroll
    for (int mi = 0; mi < 2; mi++) {
        int r0 = m0 + wm * 32 + mi * 16 + g;
        #pragma unroll
        for (int nj = 0; nj < 4; nj++) {
            int cb = wn * 32 + nj * 8 + 2 * t;
            #pragma unroll
            for (int half_ = 0; half_ < 2; half_++) {
                int gm = r0 + half_ * 8;
                if (gm >= SEQ) continue;
                float bv = bias[gm];
                #pragma unroll
                for (int q = 0; q < 2; q++) {
                    size_t idx = ((size_t)(b * SEQ + gm)) * EMB + h * HD + cb + q;
                    x1[idx] += acc[mi][nj][half_ * 2 + q] + bv;
                }
            }
        }
    }
}

// ---------------- launch ----------------
extern "C" void kernel_launch(void* const* d_in, const int* in_sizes, int n_in,
                              void* d_out, int out_size) {
    (void)in_sizes; (void)n_in; (void)out_size;
    const float* x         = (const float*)d_in[0];
    const float* qkv_w     = (const float*)d_in[1];
    const float* fc_w      = (const float*)d_in[2];
    const float* fc_b      = (const float*)d_in[3];
    const float* attn_ln_g = (const float*)d_in[4];
    const float* attn_ln_b = (const float*)d_in[5];
    const float* fc2_w     = (const float*)d_in[6];
    const float* fc2_b     = (const float*)d_in[7];
    const float* mlp_w1    = (const float*)d_in[8];
    const float* mlp_b1    = (const float*)d_in[9];
    const float* mlp_w2    = (const float*)d_in[10];
    const float* mlp_b2    = (const float*)d_in[11];
    const float* f_ln_g    = (const float*)d_in[12];
    const float* f_ln_b    = (const float*)d_in[13];
    const float* gl_ln_g   = (const float*)d_in[14];
    const float* gl_ln_b   = (const float*)d_in[15];

    float *px1, *px2;
    __half *pxn, *pqkv, *pA, *pG, *py, *ph;
    __half *pwqkv, *pwfcp, *pw1, *pw2, *pwfc2t;
    cudaGetSymbolAddress((void**)&px1,  g_x1);
    cudaGetSymbolAddress((void**)&px2,  g_x2);
    cudaGetSymbolAddress((void**)&pxn,  g_xn);
    cudaGetSymbolAddress((void**)&pqkv, g_qkv);
    cudaGetSymbolAddress((void**)&pA,   g_A);
    cudaGetSymbolAddress((void**)&pG,   g_G);
    cudaGetSymbolAddress((void**)&py,   g_y);
    cudaGetSymbolAddress((void**)&ph,   g_h);
    cudaGetSymbolAddress((void**)&pwqkv,  g_wqkv);
    cudaGetSymbolAddress((void**)&pwfcp,  g_wfcp);
    cudaGetSymbolAddress((void**)&pw1,    g_w1);
    cudaGetSymbolAddress((void**)&pw2,    g_w2);
    cudaGetSymbolAddress((void**)&pwfc2t, g_wfc2t);

    const int NE = TOK * EMB;

    prep_wT<<<CDIV(EMB*EMB3, 256), 256>>>(qkv_w, pwqkv, EMB, EMB3);
    prep_wT<<<CDIV(EMB*HIDDEN, 256), 256>>>(mlp_w1, pw1, EMB, HIDDEN);
    prep_wT<<<CDIV(HIDDEN*EMB, 256), 256>>>(mlp_w2, pw2, HIDDEN, EMB);
    prep_fcpad<<<CDIV(SPAD*SPAD, 256), 256>>>(fc_w, pwfcp);
    prep_fc2T<<<CDIV(256*KWPAD, 256), 256>>>(fc2_w, pwfc2t);

    init_copy<<<CDIV(NE, 256), 256>>>(x, px1, px2, NE);

    for (int l = 0; l < NLAYERS; ++l) {
        // y1 = x1 + attention(LN_f(x2))
        ln_row768<<<TOK, 256>>>(px2, f_ln_g + l * EMB, f_ln_b + l * EMB, pxn);
        gemm_f16<4><<<dim3(EMB3/128, CDIV(TOK,128)), 256>>>(
            pxn, pwqkv, nullptr, nullptr, pqkv, nullptr, EMB3, TOK, EMB3, EMB);
        kg_f16<<<dim3(2, BH), 256>>>(pwfcp, pqkv, pG);
        qg_f16<<<dim3(2, 2, BH), 256>>>(pqkv, pG, fc_b, pA);
        ln_softmax<<<ROWSA / 8, 256>>>(pA, attn_ln_g, attn_ln_b);
        pv_f16<<<dim3(2, BH), 256>>>(pA, pqkv, py);
        out_f16<<<dim3(2, BH), 256>>>(pwfc2t, py, fc2_b, px1);
        // y2 = x2 + mlp(LN_g(y1))
        ln_row768<<<TOK, 256>>>(px1, gl_ln_g + l * EMB, gl_ln_b + l * EMB, pxn);
        gemm_f16<2><<<dim3(HIDDEN/128, CDIV(TOK,128)), 256>>>(
            pxn, pw1, mlp_b1, nullptr, ph, nullptr, HIDDEN, TOK, HIDDEN, EMB);
        gemm_f16<3><<<dim3(EMB/128, CDIV(TOK,128)), 256>>>(
            ph, pw2, mlp_b2, px2, nullptr, px2, EMB, TOK, EMB, HIDDEN);
    }

    finalize_k<<<CDIV(NE, 256), 256>>>(px1, px2, (float*)d_out, NE);
}

// round 14
// speedup vs baseline: 1.1274x; 1.0407x over previous
#include <cuda_runtime.h>
#include <cuda_fp16.h>
#include <math.h>
#include <stdint.h>

#define BATCH   32
#define SEQ     197
#define EMB     768
#define EMB3    2304
#define HEADS   12
#define HD      64
#define KW      197
#define NLAYERS 12
#define HIDDEN  3072
#define TOK     (BATCH*SEQ)       // 6304
#define BH      (BATCH*HEADS)     // 384
#define ROWSA   (BH*SEQ)          // 75648
#define SPAD    224
#define KWPAD   208

#define CDIV(a,b) (((a)+(b)-1)/(b))

// ---------------- scratch ----------------
static __device__ float  g_x1 [TOK*EMB];
static __device__ float  g_x2 [TOK*EMB];
static __device__ __half g_xn [TOK*EMB];
static __device__ __half g_qkv[TOK*EMB3];
static __device__ __half g_A  [(size_t)BH*SEQ*SPAD];   // zero-init; pad cols stay 0
static __device__ __half g_G  [(size_t)BH*SPAD*HD];
static __device__ __half g_y  [BH*KW*HD];
static __device__ __half g_h  [TOK*HIDDEN];
static __device__ __half g_wqkv [EMB3*EMB];
static __device__ __half g_wfcp [SPAD*SPAD];      // fc_w zero-padded [m][j]
static __device__ __half g_w1   [HIDDEN*EMB];
static __device__ __half g_w2   [EMB*HIDDEN];
static __device__ __half g_wfc2t[256*KWPAD];

// ---------------- helpers ----------------
__device__ __forceinline__ void cpasync16(uint32_t dst, const void* src, int srcbytes) {
    asm volatile("cp.async.cg.shared.global [%0], [%1], 16, %2;\n"
                 :: "r"(dst), "l"(src), "r"(srcbytes));
}
__device__ __forceinline__ void cp_commit() { asm volatile("cp.async.commit_group;\n"); }
__device__ __forceinline__ void cp_wait0() { asm volatile("cp.async.wait_group 0;\n"); }
__device__ __forceinline__ void cp_wait1() { asm volatile("cp.async.wait_group 1;\n"); }

#define MMA_F16(acc, afr, bfr)                                               \
    asm volatile(                                                            \
        "mma.sync.aligned.m16n8k16.row.col.f32.f16.f16.f32 "                 \
        "{%0,%1,%2,%3}, {%4,%5,%6,%7}, {%8,%9}, {%0,%1,%2,%3};\n"            \
        : "+f"((acc)[0]), "+f"((acc)[1]), "+f"((acc)[2]), "+f"((acc)[3])     \
        : "r"((afr)[0]), "r"((afr)[1]), "r"((afr)[2]), "r"((afr)[3]),        \
          "r"((bfr)[0]), "r"((bfr)[1]))

#define LDSM_X4(r0, r1, r2, r3, addr)                                        \
    asm volatile("ldmatrix.sync.aligned.m8n8.x4.shared.b16 "                 \
                 "{%0,%1,%2,%3}, [%4];"                                      \
                 : "=r"(r0), "=r"(r1), "=r"(r2), "=r"(r3) : "r"(addr))

#define LDSM_X4_T(r0, r1, r2, r3, addr)                                      \
    asm volatile("ldmatrix.sync.aligned.m8n8.x4.trans.shared.b16 "           \
                 "{%0,%1,%2,%3}, [%4];"                                      \
                 : "=r"(r0), "=r"(r1), "=r"(r2), "=r"(r3) : "r"(addr))

// ---------------- elementwise / prep ----------------
__global__ void init_copy(const float* __restrict__ x, float* __restrict__ x1,
                          float* __restrict__ x2, int n) {
    int i = blockIdx.x * blockDim.x + threadIdx.x;
    if (i < n) { float v = x[i]; x1[i] = v; x2[i] = v; }
}

__global__ void finalize_k(const float* __restrict__ x1, const float* __restrict__ x2,
                           float* __restrict__ out, int n) {
    int i = blockIdx.x * blockDim.x + threadIdx.x;
    if (i < n) out[i] = 0.5f * (x1[i] + x2[i]);
}

__global__ void prep_wT(const float* __restrict__ s, __half* __restrict__ d,
                        int K, int N) {
    int i = blockIdx.x * blockDim.x + threadIdx.x;
    if (i < N * K) {
        int n = i / K, k = i % K;
        d[i] = __float2half_rn(s[(size_t)k * N + n]);
    }
}

__global__ void prep_fcpad(const float* __restrict__ s, __half* __restrict__ d) {
    int i = blockIdx.x * blockDim.x + threadIdx.x;
    if (i < SPAD * SPAD) {
        int m = i / SPAD, j = i % SPAD;
        d[i] = (m < SEQ && j < KW) ? __float2half_rn(s[m * KW + j]) : __float2half(0.f);
    }
}

__global__ void prep_fc2T(const float* __restrict__ s, __half* __restrict__ d) {
    int i = blockIdx.x * blockDim.x + threadIdx.x;
    if (i < 256 * KWPAD) {
        int n2 = i / KWPAD, k = i % KWPAD;
        d[i] = (n2 < SEQ && k < KW) ? __float2half_rn(s[k * SEQ + n2]) : __float2half(0.f);
    }
}

// ---------------- layernorm rows of 768 -> half ----------------
__global__ void ln_row768(const float* __restrict__ x, const float* __restrict__ g,
                          const float* __restrict__ b, __half* __restrict__ out) {
    int row = blockIdx.x;
    const float* xr = x + (size_t)row * EMB;
    __half* orow = out + (size_t)row * EMB;
    int tid = threadIdx.x;
    float s = 0.f, ss = 0.f;
    for (int i = tid; i < EMB; i += 256) { float v = xr[i]; s += v; ss += v * v; }
    __shared__ float rs[8], rss[8];
    #pragma unroll
    for (int o = 16; o; o >>= 1) {
        s  += __shfl_xor_sync(0xffffffffu, s,  o);
        ss += __shfl_xor_sync(0xffffffffu, ss, o);
    }
    if ((tid & 31) == 0) { rs[tid >> 5] = s; rss[tid >> 5] = ss; }
    __syncthreads();
    if (tid < 32) {
        float a = (tid < 8) ? rs[tid]  : 0.f;
        float c = (tid < 8) ? rss[tid] : 0.f;
        #pragma unroll
        for (int o = 4; o; o >>= 1) {
            a += __shfl_xor_sync(0xffffffffu, a, o);
            c += __shfl_xor_sync(0xffffffffu, c, o);
        }
        if (tid == 0) { rs[0] = a; rss[0] = c; }
    }
    __syncthreads();
    float mu  = rs[0] * (1.0f / EMB);
    float var = rss[0] * (1.0f / EMB) - mu * mu;
    float inv = rsqrtf(var + 1e-5f);
    for (int i = tid; i < EMB; i += 256)
        orow[i] = __float2half_rn((xr[i] - mu) * inv * g[i] + b[i]);
}

// ================= fp16 GEMM (R7-proven): C = A[M,K] @ Bt[N,K]^T ===========
#define GST 40
#define GSTG (128*GST)

template <int EPI>
__global__ void __launch_bounds__(256) gemm_f16(
    const __half* __restrict__ A, const __half* __restrict__ B,
    const float* __restrict__ bias, const float* __restrict__ res,
    __half* __restrict__ Ch, float* __restrict__ Cf,
    int ldc, int M, int N, int K)
{
    __shared__ __half As[3 * GSTG];
    __shared__ __half Bs[3 * GSTG];
    const int tid  = threadIdx.x;
    const int warp = tid >> 5, lane = tid & 31;
    const int wm = warp >> 2, wn = warp & 3;
    const int g = lane >> 2, t = lane & 3;
    const int m0 = blockIdx.y * 128, n0 = blockIdx.x * 128;

    const uint32_t as_u = (uint32_t)__cvta_generic_to_shared(As);
    const uint32_t bs_u = (uint32_t)__cvta_generic_to_shared(Bs);

    const int r0i = tid >> 2, seg = (tid & 3) * 8;
    const int r1i = (tid + 256) >> 2;

    const int lrowA = (lane & 7) + ((lane >> 3) & 1) * 8;
    const int lcolA = ((lane >> 4) & 1) * 8;
    const int lrowB = (lane & 7) + ((lane >> 4) & 1) * 8;
    const int lcolB = ((lane >> 3) & 1) * 8;

    float acc[4][4][4];
    #pragma unroll
    for (int i = 0; i < 4; i++)
        #pragma unroll
        for (int j = 0; j < 4; j++)
            #pragma unroll
            for (int r = 0; r < 4; r++) acc[i][j][r] = 0.f;

    const int nch = K / 32;

    #pragma unroll
    for (int p = 0; p < 2; p++) {
        const int k0 = p * 32;
        const int so = p * GSTG;
        cpasync16(as_u + (uint32_t)(so + r0i * GST + seg) * 2,
                  A + (size_t)(m0 + r0i) * K + k0 + seg, (m0 + r0i < M) ? 16 : 0);
        cpasync16(as_u + (uint32_t)(so + r1i * GST + seg) * 2,
                  A + (size_t)(m0 + r1i) * K + k0 + seg, (m0 + r1i < M) ? 16 : 0);
        cpasync16(bs_u + (uint32_t)(so + r0i * GST + seg) * 2,
                  B + (size_t)(n0 + r0i) * K + k0 + seg, 16);
        cpasync16(bs_u + (uint32_t)(so + r1i * GST + seg) * 2,
                  B + (size_t)(n0 + r1i) * K + k0 + seg, 16);
        cp_commit();
    }

    int st_c = 0, st_p = 2;
    for (int c = 0; c < nch; ++c) {
        if (c + 1 < nch) cp_wait1(); else cp_wait0();
        __syncthreads();

        if (c + 2 < nch) {
            const int k0 = (c + 2) * 32;
            const int so = st_p * GSTG;
            cpasync16(as_u + (uint32_t)(so + r0i * GST + seg) * 2,
                      A + (size_t)(m0 + r0i) * K + k0 + seg, (m0 + r0i < M) ? 16 : 0);
            cpasync16(as_u + (uint32_t)(so + r1i * GST + seg) * 2,
                      A + (size_t)(m0 + r1i) * K + k0 + seg, (m0 + r1i < M) ? 16 : 0);
            cpasync16(bs_u + (uint32_t)(so + r0i * GST + seg) * 2,
                      B + (size_t)(n0 + r0i) * K + k0 + seg, 16);
            cpasync16(bs_u + (uint32_t)(so + r1i * GST + seg) * 2,
                      B + (size_t)(n0 + r1i) * K + k0 + seg, 16);
            cp_commit();
        }

        const uint32_t a_base = as_u + (uint32_t)(st_c * GSTG) * 2;
        const uint32_t b_base = bs_u + (uint32_t)(st_c * GSTG) * 2;

        #pragma unroll
        for (int kk = 0; kk < 2; ++kk) {
            const int kb = kk * 16;
            uint32_t afr[4][4], bfr[4][2];
            #pragma unroll
            for (int mi = 0; mi < 4; mi++) {
                int m = wm * 64 + mi * 16;
                uint32_t addr = a_base + (uint32_t)((m + lrowA) * GST + kb + lcolA) * 2;
                LDSM_X4(afr[mi][0], afr[mi][1], afr[mi][2], afr[mi][3], addr);
            }
            #pragma unroll
            for (int njp = 0; njp < 2; njp++) {
                int n = wn * 32 + njp * 16;
                uint32_t addr = b_base + (uint32_t)((n + lrowB) * GST + kb + lcolB) * 2;
                LDSM_X4(bfr[njp * 2][0], bfr[njp * 2][1],
                        bfr[njp * 2 + 1][0], bfr[njp * 2 + 1][1], addr);
            }
            #pragma unroll
            for (int mi = 0; mi < 4; mi++)
                #pragma unroll
                for (int nj = 0; nj < 4; nj++)
                    MMA_F16(acc[mi][nj], afr[mi], bfr[nj]);
        }
        st_c = (st_c == 2) ? 0 : st_c + 1;
        st_p = (st_p == 2) ? 0 : st_p + 1;
    }

    #pragma unroll
    for (int mi = 0; mi < 4; mi++) {
        int r0 = m0 + wm * 64 + mi * 16 + g;
        #pragma unroll
        for (int nj = 0; nj < 4; nj++) {
            int cb = n0 + wn * 32 + nj * 8 + 2 * t;
            #pragma unroll
            for (int half_ = 0; half_ < 2; half_++) {
                int gm = r0 + half_ * 8;
                if (gm >= M) continue;
                #pragma unroll
                for (int q = 0; q < 2; q++) {
                    int gn = cb + q;
                    if (gn >= N) continue;
                    float v = acc[mi][nj][half_ * 2 + q];
                    if (EPI == 1 || EPI == 2 || EPI == 3) v += bias[gn];
                    if (EPI == 2)
                        v = 0.5f * v * (1.0f + erff(v * 0.70710678118654752f));
                    if (EPI == 3)
                        Cf[(size_t)gm * ldc + gn] = v + res[(size_t)gm * ldc + gn];
                    else
                        Ch[(size_t)gm * ldc + gn] = __float2half_rn(v);
                }
            }
        }
    }
}

// ---------------- kg: Gt[z,j,d] = 0.125 * sum_m fc_w[m,j] K[m,d] -----------
__global__ void __launch_bounds__(256) kg_f16(const __half* __restrict__ Wp,
                                              const __half* __restrict__ qkv,
                                              __half* __restrict__ G)
{
    __shared__ __half Ps[16 * 136];
    __shared__ __half Ks[16 * 72];
    const int z = blockIdx.y, b = z / HEADS, h = z % HEADS;
    const __half* Kb = qkv + (size_t)b * SEQ * EMB3 + h * HD + EMB;
    const int m0 = blockIdx.x * 128;   // j range
    const int tid = threadIdx.x;
    const int warp = tid >> 5, lane = tid & 31;
    const int wm = warp >> 1, wn = warp & 1;
    const int g = lane >> 2, t = lane & 3;
    const uint32_t ps_u = (uint32_t)__cvta_generic_to_shared(Ps);
    const uint32_t vs_u = (uint32_t)__cvta_generic_to_shared(Ks);

    const int arow = (lane & 7) + ((lane >> 4) << 3);
    const int acol8 = ((lane >> 3) & 1) << 3;
    const int brow = (lane & 7) + (((lane >> 3) & 1) << 3);
    const int bcol8 = (lane >> 4) << 3;

    float acc[2][4][4];
    #pragma unroll
    for (int i = 0; i < 2; i++)
        #pragma unroll
        for (int j = 0; j < 4; j++)
            #pragma unroll
            for (int r = 0; r < 4; r++) acc[i][j][r] = 0.f;

    for (int c = 0; c < KWPAD / 16; ++c) {
        const int k0 = c * 16;
        {
            int r = tid >> 4, sg = (tid & 15) * 8;
            cpasync16(ps_u + (size_t)(r * 136 + sg) * 2,
                      Wp + (size_t)(k0 + r) * SPAD + m0 + sg,
                      (k0 + r < SEQ && m0 + sg < SPAD) ? 16 : 0);
        }
        if (tid < 128) {
            int r = tid >> 3, sg = (tid & 7) * 8;
            cpasync16(vs_u + (size_t)(r * 72 + sg) * 2,
                      Kb + (size_t)(k0 + r) * EMB3 + sg, (k0 + r < SEQ) ? 16 : 0);
        }
        cp_commit(); cp_wait0();
        __syncthreads();

        uint32_t afr[2][4], bfr[4][2];
        #pragma unroll
        for (int mi = 0; mi < 2; mi++) {
            uint32_t addr = ps_u + (size_t)(arow * 136 + wm * 32 + mi * 16 + acol8) * 2;
            LDSM_X4_T(afr[mi][0], afr[mi][1], afr[mi][2], afr[mi][3], addr);
        }
        #pragma unroll
        for (int njp = 0; njp < 2; njp++) {
            uint32_t addr = vs_u + (size_t)(brow * 72 + wn * 32 + njp * 16 + bcol8) * 2;
            LDSM_X4_T(bfr[njp * 2][0], bfr[njp * 2][1],
                      bfr[njp * 2 + 1][0], bfr[njp * 2 + 1][1], addr);
        }
        #pragma unroll
        for (int mi = 0; mi < 2; mi++)
            #pragma unroll
            for (int nj = 0; nj < 4; nj++)
                MMA_F16(acc[mi][nj], afr[mi], bfr[nj]);
        __syncthreads();
    }

    __half* Gz = G + (size_t)z * SPAD * HD;
    #pragma unroll
    for (int mi = 0; mi < 2; mi++) {
        int r0 = m0 + wm * 32 + mi * 16 + g;
        #pragma unroll
        for (int nj = 0; nj < 4; nj++) {
            int cb = wn * 32 + nj * 8 + 2 * t;
            #pragma unroll
            for (int half_ = 0; half_ < 2; half_++) {
                int gm = r0 + half_ * 8;
                if (gm >= SPAD) continue;
                #pragma unroll
                for (int q = 0; q < 2; q++)
                    Gz[(size_t)gm * HD + cb + q] =
                        __float2half_rn(acc[mi][nj][half_ * 2 + q] * 0.125f);
            }
        }
    }
}

// ===== qgs: A[z,n,j] = softmax_j( LN_j( sum_d Q[n,d] Gt[j,d] + fc_b ) ) ====
// Block: 64 q-rows x 224 cols (full KW row). 8 warps = 2m x 4n, warp 32x56.
// acc[2][7][4] = 56 regs. Epilogue = R6's verified 3-phase row reduction.
__global__ void __launch_bounds__(256) qgs_f16(
    const __half* __restrict__ qkv, const __half* __restrict__ G,
    const float* __restrict__ fc_b,
    const float* __restrict__ ln_g, const float* __restrict__ ln_b,
    __half* __restrict__ Aout)
{
    __shared__ __half Qs[64 * 72];
    __shared__ __half Gs[224 * 72];
    __shared__ float red_s[64 * 4];
    __shared__ float red_ss[64 * 4];
    __shared__ float biasf[224], lngs[224], lnbs[224];

    const int z = blockIdx.y, b = z / HEADS, h = z % HEADS;
    const int m0 = blockIdx.x * 64;
    const __half* qb = qkv + (size_t)b * SEQ * EMB3 + h * HD;
    const __half* Gb = G + (size_t)z * SPAD * HD;

    const int tid = threadIdx.x;
    const int warp = tid >> 5, lane = tid & 31;
    const int wm = warp >> 2, wn = warp & 3;
    const int g = lane >> 2, t = lane & 3;
    const uint32_t qs_u = (uint32_t)__cvta_generic_to_shared(Qs);
    const uint32_t gs_u = (uint32_t)__cvta_generic_to_shared(Gs);

    for (int i = tid; i < 224; i += 256) {
        biasf[i] = (i < KW) ? fc_b[i] : 0.f;
        lngs[i]  = (i < KW) ? ln_g[i] : 0.f;
        lnbs[i]  = (i < KW) ? ln_b[i] : 0.f;
    }

    #pragma unroll
    for (int i = 0; i < 2; i++) {
        int f = tid + i * 256;                  // 0..511 -> 64 rows x 8 segs
        int r = f >> 3, sg = (f & 7) * 8;
        cpasync16(qs_u + (uint32_t)(r * 72 + sg) * 2,
                  qb + (size_t)(m0 + r) * EMB3 + sg, (m0 + r < SEQ) ? 16 : 0);
    }
    #pragma unroll
    for (int i = 0; i < 7; i++) {
        int f = tid + i * 256;                  // 0..1791 -> 224 rows x 8 segs
        int r = f >> 3, sg = (f & 7) * 8;
        cpasync16(gs_u + (uint32_t)(r * 72 + sg) * 2,
                  Gb + (size_t)r * HD + sg, 16);
    }
    cp_commit(); cp_wait0();
    __syncthreads();

    float acc[2][7][4];
    #pragma unroll
    for (int i = 0; i < 2; i++)
        #pragma unroll
        for (int j = 0; j < 7; j++)
            #pragma unroll
            for (int r = 0; r < 4; r++) acc[i][j][r] = 0.f;

    const uint32_t* qs32 = (const uint32_t*)Qs;
    const uint32_t* gs32 = (const uint32_t*)Gs;
    #pragma unroll
    for (int kk = 0; kk < 4; ++kk) {
        const int kb2 = kk * 8;
        uint32_t afr[2][4], bfr[7][2];
        #pragma unroll
        for (int mi = 0; mi < 2; mi++) {
            int m = wm * 32 + mi * 16 + g;
            afr[mi][0] = qs32[(m    ) * 36 + kb2 + t];
            afr[mi][1] = qs32[(m + 8) * 36 + kb2 + t];
            afr[mi][2] = qs32[(m    ) * 36 + kb2 + t + 4];
            afr[mi][3] = qs32[(m + 8) * 36 + kb2 + t + 4];
        }
        #pragma unroll
        for (int nj = 0; nj < 7; nj++) {
            int n = wn * 56 + nj * 8 + g;
            bfr[nj][0] = gs32[n * 36 + kb2 + t];
            bfr[nj][1] = gs32[n * 36 + kb2 + t + 4];
        }
        #pragma unroll
        for (int mi = 0; mi < 2; mi++)
            #pragma unroll
            for (int nj = 0; nj < 7; nj++)
                MMA_F16(acc[mi][nj], afr[mi], bfr[nj]);
    }

    // ---- epilogue: +bias, LN(row over KW), softmax(row) ----
    float mu_[2][2], inv_[2][2];
    #pragma unroll
    for (int mi = 0; mi < 2; mi++)
        #pragma unroll
        for (int hf = 0; hf < 2; hf++) {
            float s = 0.f, ss = 0.f;
            #pragma unroll
            for (int nj = 0; nj < 7; nj++)
                #pragma unroll
                for (int q = 0; q < 2; q++) {
                    int gn = wn * 56 + nj * 8 + 2 * t + q;
                    if (gn < KW) {
                        float v = acc[mi][nj][hf * 2 + q] + biasf[gn];
                        acc[mi][nj][hf * 2 + q] = v;
                        s += v; ss += v * v;
                    }
                }
            s  += __shfl_xor_sync(0xffffffffu, s, 1);
            s  += __shfl_xor_sync(0xffffffffu, s, 2);
            ss += __shfl_xor_sync(0xffffffffu, ss, 1);
            ss += __shfl_xor_sync(0xffffffffu, ss, 2);
            if (t == 0) {
                int row = wm * 32 + mi * 16 + g + 8 * hf;
                red_s [row * 4 + wn] = s;
                red_ss[row * 4 + wn] = ss;
            }
        }
    __syncthreads();
    #pragma unroll
    for (int mi = 0; mi < 2; mi++)
        #pragma unroll
        for (int hf = 0; hf < 2; hf++) {
            int row = wm * 32 + mi * 16 + g + 8 * hf;
            float s  = red_s [row * 4] + red_s [row * 4 + 1]
                     + red_s [row * 4 + 2] + red_s [row * 4 + 3];
            float ss = red_ss[row * 4] + red_ss[row * 4 + 1]
                     + red_ss[row * 4 + 2] + red_ss[row * 4 + 3];
            float mu = s * (1.0f / KW);
            float var = ss * (1.0f / KW) - mu * mu;
            mu_[mi][hf] = mu;
            inv_[mi][hf] = rsqrtf(var + 1e-5f);
        }
    __syncthreads();
    float mx_[2][2];
    #pragma unroll
    for (int mi = 0; mi < 2; mi++)
        #pragma unroll
        for (int hf = 0; hf < 2; hf++) {
            float mx = -1e30f;
            #pragma unroll
            for (int nj = 0; nj < 7; nj++)
                #pragma unroll
                for (int q = 0; q < 2; q++) {
                    int gn = wn * 56 + nj * 8 + 2 * t + q;
                    if (gn < KW) {
                        float zv = (acc[mi][nj][hf * 2 + q] - mu_[mi][hf]) * inv_[mi][hf]
                                   * lngs[gn] + lnbs[gn];
                        acc[mi][nj][hf * 2 + q] = zv;
                        mx = fmaxf(mx, zv);
                    }
                }
            mx = fmaxf(mx, __shfl_xor_sync(0xffffffffu, mx, 1));
            mx = fmaxf(mx, __shfl_xor_sync(0xffffffffu, mx, 2));
            if (t == 0) {
                int row = wm * 32 + mi * 16 + g + 8 * hf;
                red_s[row * 4 + wn] = mx;
            }
        }
    __syncthreads();
    #pragma unroll
    for (int mi = 0; mi < 2; mi++)
        #pragma unroll
        for (int hf = 0; hf < 2; hf++) {
            int row = wm * 32 + mi * 16 + g + 8 * hf;
            mx_[mi][hf] = fmaxf(fmaxf(red_s[row * 4], red_s[row * 4 + 1]),
                                fmaxf(red_s[row * 4 + 2], red_s[row * 4 + 3]));
        }
    __syncthreads();
    float rinv_[2][2];
    #pragma unroll
    for (int mi = 0; mi < 2; mi++)
        #pragma unroll
        for (int hf = 0; hf < 2; hf++) {
            float s = 0.f;
            #pragma unroll
            for (int nj = 0; nj < 7; nj++)
                #pragma unroll
                for (int q = 0; q < 2; q++) {
                    int gn = wn * 56 + nj * 8 + 2 * t + q;
                    if (gn < KW) {
                        float e = __expf(acc[mi][nj][hf * 2 + q] - mx_[mi][hf]);
                        acc[mi][nj][hf * 2 + q] = e;
                        s += e;
                    }
                }
            s += __shfl_xor_sync(0xffffffffu, s, 1);
            s += __shfl_xor_sync(0xffffffffu, s, 2);
            if (t == 0) {
                int row = wm * 32 + mi * 16 + g + 8 * hf;
                red_s[row * 4 + wn] = s;
            }
        }
    __syncthreads();
    #pragma unroll
    for (int mi = 0; mi < 2; mi++)
        #pragma unroll
        for (int hf = 0; hf < 2; hf++) {
            int row = wm * 32 + mi * 16 + g + 8 * hf;
            rinv_[mi][hf] = 1.0f / (red_s[row * 4] + red_s[row * 4 + 1]
                                  + red_s[row * 4 + 2] + red_s[row * 4 + 3]);
        }
    __half* Az = Aout + (size_t)z * SEQ * SPAD;
    #pragma unroll
    for (int mi = 0; mi < 2; mi++)
        #pragma unroll
        for (int hf = 0; hf < 2; hf++) {
            int gm = m0 + wm * 32 + mi * 16 + g + 8 * hf;
            if (gm >= SEQ) continue;
            #pragma unroll
            for (int nj = 0; nj < 7; nj++) {
                int gn0 = wn * 56 + nj * 8 + 2 * t;
                float p0 = (gn0     < KW) ? acc[mi][nj][hf * 2    ] * rinv_[mi][hf] : 0.f;
                float p1 = (gn0 + 1 < KW) ? acc[mi][nj][hf * 2 + 1] * rinv_[mi][hf] : 0.f;
                *(__half2*)(Az + (size_t)gm * SPAD + gn0) = __floats2half2_rn(p0, p1);
            }
        }
}

// ---------------- P^T V fp16 ------------------------------------------------
__global__ void __launch_bounds__(256) pv_f16(const __half* __restrict__ A,
                                              const __half* __restrict__ qkv,
                                              __half* __restrict__ y)
{
    __shared__ __half Ps[16 * 136];
    __shared__ __half Vs[16 * 72];
    const int z = blockIdx.y, b = z / HEADS, h = z % HEADS;
    const __half* Ab = A + (size_t)z * SEQ * SPAD;
    const __half* Vb = qkv + (size_t)b * SEQ * EMB3 + h * HD + 2 * EMB;
    const int m0 = blockIdx.x * 128;
    const int tid = threadIdx.x;
    const int warp = tid >> 5, lane = tid & 31;
    const int wm = warp >> 1, wn = warp & 1;
    const int g = lane >> 2, t = lane & 3;
    const uint32_t ps_u = (uint32_t)__cvta_generic_to_shared(Ps);
    const uint32_t vs_u = (uint32_t)__cvta_generic_to_shared(Vs);

    const int arow = (lane & 7) + ((lane >> 4) << 3);
    const int acol8 = ((lane >> 3) & 1) << 3;
    const int brow = (lane & 7) + (((lane >> 3) & 1) << 3);
    const int bcol8 = (lane >> 4) << 3;

    float acc[2][4][4];
    #pragma unroll
    for (int i = 0; i < 2; i++)
        #pragma unroll
        for (int j = 0; j < 4; j++)
            #pragma unroll
            for (int r = 0; r < 4; r++) acc[i][j][r] = 0.f;

    for (int c = 0; c < KWPAD / 16; ++c) {
        const int k0 = c * 16;
        {
            int r = tid >> 4, sg = (tid & 15) * 8;
            cpasync16(ps_u + (size_t)(r * 136 + sg) * 2,
                      Ab + (size_t)(k0 + r) * SPAD + m0 + sg,
                      (k0 + r < SEQ && m0 + sg < SPAD) ? 16 : 0);
        }
        if (tid < 128) {
            int r = tid >> 3, sg = (tid & 7) * 8;
            cpasync16(vs_u + (size_t)(r * 72 + sg) * 2,
                      Vb + (size_t)(k0 + r) * EMB3 + sg, (k0 + r < SEQ) ? 16 : 0);
        }
        cp_commit(); cp_wait0();
        __syncthreads();

        uint32_t afr[2][4], bfr[4][2];
        #pragma unroll
        for (int mi = 0; mi < 2; mi++) {
            uint32_t addr = ps_u + (size_t)(arow * 136 + wm * 32 + mi * 16 + acol8) * 2;
            LDSM_X4_T(afr[mi][0], afr[mi][1], afr[mi][2], afr[mi][3], addr);
        }
        #pragma unroll
        for (int njp = 0; njp < 2; njp++) {
            uint32_t addr = vs_u + (size_t)(brow * 72 + wn * 32 + njp * 16 + bcol8) * 2;
            LDSM_X4_T(bfr[njp * 2][0], bfr[njp * 2][1],
                      bfr[njp * 2 + 1][0], bfr[njp * 2 + 1][1], addr);
        }
        #pragma unroll
        for (int mi = 0; mi < 2; mi++)
            #pragma unroll
            for (int nj = 0; nj < 4; nj++)
                MMA_F16(acc[mi][nj], afr[mi], bfr[nj]);
        __syncthreads();
    }

    __half* yz = y + (size_t)z * KW * HD;
    #pragma unroll
    for (int mi = 0; mi < 2; mi++) {
        int r0 = m0 + wm * 32 + mi * 16 + g;
        #pragma unroll
        for (int nj = 0; nj < 4; nj++) {
            int cb = wn * 32 + nj * 8 + 2 * t;
            #pragma unroll
            for (int half_ = 0; half_ < 2; half_++) {
                int gm = r0 + half_ * 8;
                if (gm >= KW) continue;
                #pragma unroll
                for (int q = 0; q < 2; q++)
                    yz[(size_t)gm * HD + cb + q] =
                        __float2half_rn(acc[mi][nj][half_ * 2 + q]);
            }
        }
    }
}

// --------- fc2: x1 += Wt @ y + bias ----------------------------------------
__global__ void __launch_bounds__(256) out_f16(const __half* __restrict__ Wt,
                                               const __half* __restrict__ y,
                                               const float* __restrict__ bias,
                                               float* __restrict__ x1)
{
    __shared__ __half As[128 * 24];
    __shared__ __half Ys[16 * 72];
    const int z = blockIdx.y, b = z / HEADS, h = z % HEADS;
    const __half* yb = y + (size_t)z * KW * HD;
    const int m0 = blockIdx.x * 128;
    const int tid = threadIdx.x;
    const int warp = tid >> 5, lane = tid & 31;
    const int wm = warp >> 1, wn = warp & 1;
    const int g = lane >> 2, t = lane & 3;
    const uint32_t as_u = (uint32_t)__cvta_generic_to_shared(As);
    const uint32_t ys_u = (uint32_t)__cvta_generic_to_shared(Ys);

    const int brow = (lane & 7) + (((lane >> 3) & 1) << 3);
    const int bcol8 = (lane >> 4) << 3;

    float acc[2][4][4];
    #pragma unroll
    for (int i = 0; i < 2; i++)
        #pragma unroll
        for (int j = 0; j < 4; j++)
            #pragma unroll
            for (int r = 0; r < 4; r++) acc[i][j][r] = 0.f;

    for (int c = 0; c < KWPAD / 16; ++c) {
        const int k0 = c * 16;
        {
            int r = tid >> 1, sg = (tid & 1) * 8;
            cpasync16(as_u + (size_t)(r * 24 + sg) * 2,
                      Wt + (size_t)(m0 + r) * KWPAD + k0 + sg, 16);
        }
        if (tid < 128) {
            int r = tid >> 3, sg = (tid & 7) * 8;
            cpasync16(ys_u + (size_t)(r * 72 + sg) * 2,
                      yb + (size_t)(k0 + r) * HD + sg, (k0 + r < KW) ? 16 : 0);
        }
        cp_commit(); cp_wait0();
        __syncthreads();

        const uint32_t* as32 = (const uint32_t*)As;
        uint32_t afr[2][4], bfr[4][2];
        #pragma unroll
        for (int mi = 0; mi < 2; mi++) {
            int m = wm * 32 + mi * 16 + g;
            afr[mi][0] = as32[(m    ) * 12 + t];
            afr[mi][1] = as32[(m + 8) * 12 + t];
            afr[mi][2] = as32[(m    ) * 12 + t + 4];
            afr[mi][3] = as32[(m + 8) * 12 + t + 4];
        }
        #pragma unroll
        for (int njp = 0; njp < 2; njp++) {
            uint32_t addr = ys_u + (size_t)(brow * 72 + wn * 32 + njp * 16 + bcol8) * 2;
            LDSM_X4_T(bfr[njp * 2][0], bfr[njp * 2][1],
                      bfr[njp * 2 + 1][0], bfr[njp * 2 + 1][1], addr);
        }
        #pragma unroll
        for (int mi = 0; mi < 2; mi++)
            #pragma unroll
            for (int nj = 0; nj < 4; nj++)
                MMA_F16(acc[mi][nj], afr[mi], bfr[nj]);
        __syncthreads();
    }

    #pragma unroll
    for (int mi = 0; mi < 2; mi++) {
        int r0 = m0 + wm * 32 + mi * 16 + g;
        #pragma unroll
        for (int nj = 0; nj < 4; nj++) {
            int cb = wn * 32 + nj * 8 + 2 * t;
            #pragma unroll
            for (int half_ = 0; half_ < 2; half_++) {
                int gm = r0 + half_ * 8;
                if (gm >= SEQ) continue;
                float bv = bias[gm];
                #pragma unroll
                for (int q = 0; q < 2; q++) {
                    size_t idx = ((size_t)(b * SEQ + gm)) * EMB + h * HD + cb + q;
                    x1[idx] += acc[mi][nj][half_ * 2 + q] + bv;
                }
            }
        }
    }
}

// ---------------- launch ----------------
extern "C" void kernel_launch(void* const* d_in, const int* in_sizes, int n_in,
                              void* d_out, int out_size) {
    (void)in_sizes; (void)n_in; (void)out_size;
    const float* x         = (const float*)d_in[0];
    const float* qkv_w     = (const float*)d_in[1];
    const float* fc_w      = (const float*)d_in[2];
    const float* fc_b      = (const float*)d_in[3];
    const float* attn_ln_g = (const float*)d_in[4];
    const float* attn_ln_b = (const float*)d_in[5];
    const float* fc2_w     = (const float*)d_in[6];
    const float* fc2_b     = (const float*)d_in[7];
    const float* mlp_w1    = (const float*)d_in[8];
    const float* mlp_b1    = (const float*)d_in[9];
    const float* mlp_w2    = (const float*)d_in[10];
    const float* mlp_b2    = (const float*)d_in[11];
    const float* f_ln_g    = (const float*)d_in[12];
    const float* f_ln_b    = (const float*)d_in[13];
    const float* gl_ln_g   = (const float*)d_in[14];
    const float* gl_ln_b   = (const float*)d_in[15];

    float *px1, *px2;
    __half *pxn, *pqkv, *pA, *pG, *py, *ph;
    __half *pwqkv, *pwfcp, *pw1, *pw2, *pwfc2t;
    cudaGetSymbolAddress((void**)&px1,  g_x1);
    cudaGetSymbolAddress((void**)&px2,  g_x2);
    cudaGetSymbolAddress((void**)&pxn,  g_xn);
    cudaGetSymbolAddress((void**)&pqkv, g_qkv);
    cudaGetSymbolAddress((void**)&pA,   g_A);
    cudaGetSymbolAddress((void**)&pG,   g_G);
    cudaGetSymbolAddress((void**)&py,   g_y);
    cudaGetSymbolAddress((void**)&ph,   g_h);
    cudaGetSymbolAddress((void**)&pwqkv,  g_wqkv);
    cudaGetSymbolAddress((void**)&pwfcp,  g_wfcp);
    cudaGetSymbolAddress((void**)&pw1,    g_w1);
    cudaGetSymbolAddress((void**)&pw2,    g_w2);
    cudaGetSymbolAddress((void**)&pwfc2t, g_wfc2t);

    const int NE = TOK * EMB;

    prep_wT<<<CDIV(EMB*EMB3, 256), 256>>>(qkv_w, pwqkv, EMB, EMB3);
    prep_wT<<<CDIV(EMB*HIDDEN, 256), 256>>>(mlp_w1, pw1, EMB, HIDDEN);
    prep_wT<<<CDIV(HIDDEN*EMB, 256), 256>>>(mlp_w2, pw2, HIDDEN, EMB);
    prep_fcpad<<<CDIV(SPAD*SPAD, 256), 256>>>(fc_w, pwfcp);
    prep_fc2T<<<CDIV(256*KWPAD, 256), 256>>>(fc2_w, pwfc2t);

    init_copy<<<CDIV(NE, 256), 256>>>(x, px1, px2, NE);

    for (int l = 0; l < NLAYERS; ++l) {
        // y1 = x1 + attention(LN_f(x2))
        ln_row768<<<TOK, 256>>>(px2, f_ln_g + l * EMB, f_ln_b + l * EMB, pxn);
        gemm_f16<4><<<dim3(EMB3/128, CDIV(TOK,128)), 256>>>(
            pxn, pwqkv, nullptr, nullptr, pqkv, nullptr, EMB3, TOK, EMB3, EMB);
        kg_f16<<<dim3(2, BH), 256>>>(pwfcp, pqkv, pG);
        qgs_f16<<<dim3(CDIV(SEQ,64), BH), 256>>>(
            pqkv, pG, fc_b, attn_ln_g, attn_ln_b, pA);
        pv_f16<<<dim3(2, BH), 256>>>(pA, pqkv, py);
        out_f16<<<dim3(2, BH), 256>>>(pwfc2t, py, fc2_b, px1);
        // y2 = x2 + mlp(LN_g(y1))
        ln_row768<<<TOK, 256>>>(px1, gl_ln_g + l * EMB, gl_ln_b + l * EMB, pxn);
        gemm_f16<2><<<dim3(HIDDEN/128, CDIV(TOK,128)), 256>>>(
            pxn, pw1, mlp_b1, nullptr, ph, nullptr, HIDDEN, TOK, HIDDEN, EMB);
        gemm_f16<3><<<dim3(EMB/128, CDIV(TOK,128)), 256>>>(
            ph, pw2, mlp_b2, px2, nullptr, px2, EMB, TOK, EMB, HIDDEN);
    }

    finalize_k<<<CDIV(NE, 256), 256>>>(px1, px2, (float*)d_out, NE);
}

// round 15
// speedup vs baseline: 1.1434x; 1.0141x over previous
#include <cuda_runtime.h>
#include <cuda_fp16.h>
#include <math.h>
#include <stdint.h>

#define BATCH   32
#define SEQ     197
#define EMB     768
#define EMB3    2304
#define HEADS   12
#define HD      64
#define KW      197
#define NLAYERS 12
#define HIDDEN  3072
#define TOK     (BATCH*SEQ)       // 6304
#define BH      (BATCH*HEADS)     // 384
#define ROWSA   (BH*SEQ)          // 75648
#define SPAD    224
#define KWPAD   208

#define CDIV(a,b) (((a)+(b)-1)/(b))

// ---------------- scratch ----------------
static __device__ float  g_x1 [TOK*EMB];
static __device__ float  g_x2 [TOK*EMB];
static __device__ __half g_xn [TOK*EMB];
static __device__ __half g_qkv[TOK*EMB3];
static __device__ __half g_A  [(size_t)BH*SEQ*SPAD];   // zero-init; pad cols stay 0
static __device__ __half g_G  [(size_t)BH*SPAD*HD];
static __device__ __half g_y  [BH*KW*HD];
static __device__ __half g_h  [TOK*HIDDEN];
static __device__ __half g_wqkv [EMB3*EMB];
static __device__ __half g_wfcp [SPAD*SPAD];      // fc_w zero-padded [m][j]
static __device__ __half g_w1   [HIDDEN*EMB];
static __device__ __half g_w2   [EMB*HIDDEN];
static __device__ __half g_wfc2t[256*KWPAD];

// ---------------- helpers ----------------
__device__ __forceinline__ void cpasync16(uint32_t dst, const void* src, int srcbytes) {
    asm volatile("cp.async.cg.shared.global [%0], [%1], 16, %2;\n"
                 :: "r"(dst), "l"(src), "r"(srcbytes));
}
__device__ __forceinline__ void cp_commit() { asm volatile("cp.async.commit_group;\n"); }
__device__ __forceinline__ void cp_wait0() { asm volatile("cp.async.wait_group 0;\n"); }
__device__ __forceinline__ void cp_wait1() { asm volatile("cp.async.wait_group 1;\n"); }

#define MMA_F16(acc, afr, bfr)                                               \
    asm volatile(                                                            \
        "mma.sync.aligned.m16n8k16.row.col.f32.f16.f16.f32 "                 \
        "{%0,%1,%2,%3}, {%4,%5,%6,%7}, {%8,%9}, {%0,%1,%2,%3};\n"            \
        : "+f"((acc)[0]), "+f"((acc)[1]), "+f"((acc)[2]), "+f"((acc)[3])     \
        : "r"((afr)[0]), "r"((afr)[1]), "r"((afr)[2]), "r"((afr)[3]),        \
          "r"((bfr)[0]), "r"((bfr)[1]))

#define LDSM_X4(r0, r1, r2, r3, addr)                                        \
    asm volatile("ldmatrix.sync.aligned.m8n8.x4.shared.b16 "                 \
                 "{%0,%1,%2,%3}, [%4];"                                      \
                 : "=r"(r0), "=r"(r1), "=r"(r2), "=r"(r3) : "r"(addr))

#define LDSM_X4_T(r0, r1, r2, r3, addr)                                      \
    asm volatile("ldmatrix.sync.aligned.m8n8.x4.trans.shared.b16 "           \
                 "{%0,%1,%2,%3}, [%4];"                                      \
                 : "=r"(r0), "=r"(r1), "=r"(r2), "=r"(r3) : "r"(addr))

// ---------------- elementwise / prep ----------------
__global__ void init_copy(const float* __restrict__ x, float* __restrict__ x1,
                          float* __restrict__ x2, int n) {
    int i = blockIdx.x * blockDim.x + threadIdx.x;
    if (i < n) { float v = x[i]; x1[i] = v; x2[i] = v; }
}

__global__ void finalize_k(const float* __restrict__ x1, const float* __restrict__ x2,
                           float* __restrict__ out, int n) {
    int i = blockIdx.x * blockDim.x + threadIdx.x;
    if (i < n) out[i] = 0.5f * (x1[i] + x2[i]);
}

__global__ void prep_wT(const float* __restrict__ s, __half* __restrict__ d,
                        int K, int N) {
    int i = blockIdx.x * blockDim.x + threadIdx.x;
    if (i < N * K) {
        int n = i / K, k = i % K;
        d[i] = __float2half_rn(s[(size_t)k * N + n]);
    }
}

__global__ void prep_fcpad(const float* __restrict__ s, __half* __restrict__ d) {
    int i = blockIdx.x * blockDim.x + threadIdx.x;
    if (i < SPAD * SPAD) {
        int m = i / SPAD, j = i % SPAD;
        d[i] = (m < SEQ && j < KW) ? __float2half_rn(s[m * KW + j]) : __float2half(0.f);
    }
}

__global__ void prep_fc2T(const float* __restrict__ s, __half* __restrict__ d) {
    int i = blockIdx.x * blockDim.x + threadIdx.x;
    if (i < 256 * KWPAD) {
        int n2 = i / KWPAD, k = i % KWPAD;
        d[i] = (n2 < SEQ && k < KW) ? __float2half_rn(s[k * SEQ + n2]) : __float2half(0.f);
    }
}

// ---------------- layernorm rows of 768 -> half ----------------
__global__ void ln_row768(const float* __restrict__ x, const float* __restrict__ g,
                          const float* __restrict__ b, __half* __restrict__ out) {
    int row = blockIdx.x;
    const float* xr = x + (size_t)row * EMB;
    __half* orow = out + (size_t)row * EMB;
    int tid = threadIdx.x;
    float s = 0.f, ss = 0.f;
    for (int i = tid; i < EMB; i += 256) { float v = xr[i]; s += v; ss += v * v; }
    __shared__ float rs[8], rss[8];
    #pragma unroll
    for (int o = 16; o; o >>= 1) {
        s  += __shfl_xor_sync(0xffffffffu, s,  o);
        ss += __shfl_xor_sync(0xffffffffu, ss, o);
    }
    if ((tid & 31) == 0) { rs[tid >> 5] = s; rss[tid >> 5] = ss; }
    __syncthreads();
    if (tid < 32) {
        float a = (tid < 8) ? rs[tid]  : 0.f;
        float c = (tid < 8) ? rss[tid] : 0.f;
        #pragma unroll
        for (int o = 4; o; o >>= 1) {
            a += __shfl_xor_sync(0xffffffffu, a, o);
            c += __shfl_xor_sync(0xffffffffu, c, o);
        }
        if (tid == 0) { rs[0] = a; rss[0] = c; }
    }
    __syncthreads();
    float mu  = rs[0] * (1.0f / EMB);
    float var = rss[0] * (1.0f / EMB) - mu * mu;
    float inv = rsqrtf(var + 1e-5f);
    for (int i = tid; i < EMB; i += 256)
        orow[i] = __float2half_rn((xr[i] - mu) * inv * g[i] + b[i]);
}

// ================= fp16 GEMM (R7-proven): C = A[M,K] @ Bt[N,K]^T ===========
#define GST 40
#define GSTG (128*GST)

template <int EPI>
__global__ void __launch_bounds__(256) gemm_f16(
    const __half* __restrict__ A, const __half* __restrict__ B,
    const float* __restrict__ bias, const float* __restrict__ res,
    __half* __restrict__ Ch, float* __restrict__ Cf,
    int ldc, int M, int N, int K)
{
    __shared__ __half As[3 * GSTG];
    __shared__ __half Bs[3 * GSTG];
    const int tid  = threadIdx.x;
    const int warp = tid >> 5, lane = tid & 31;
    const int wm = warp >> 2, wn = warp & 3;
    const int g = lane >> 2, t = lane & 3;
    const int m0 = blockIdx.y * 128, n0 = blockIdx.x * 128;

    const uint32_t as_u = (uint32_t)__cvta_generic_to_shared(As);
    const uint32_t bs_u = (uint32_t)__cvta_generic_to_shared(Bs);

    const int r0i = tid >> 2, seg = (tid & 3) * 8;
    const int r1i = (tid + 256) >> 2;

    const int lrowA = (lane & 7) + ((lane >> 3) & 1) * 8;
    const int lcolA = ((lane >> 4) & 1) * 8;
    const int lrowB = (lane & 7) + ((lane >> 4) & 1) * 8;
    const int lcolB = ((lane >> 3) & 1) * 8;

    float acc[4][4][4];
    #pragma unroll
    for (int i = 0; i < 4; i++)
        #pragma unroll
        for (int j = 0; j < 4; j++)
            #pragma unroll
            for (int r = 0; r < 4; r++) acc[i][j][r] = 0.f;

    const int nch = K / 32;

    #pragma unroll
    for (int p = 0; p < 2; p++) {
        const int k0 = p * 32;
        const int so = p * GSTG;
        cpasync16(as_u + (uint32_t)(so + r0i * GST + seg) * 2,
                  A + (size_t)(m0 + r0i) * K + k0 + seg, (m0 + r0i < M) ? 16 : 0);
        cpasync16(as_u + (uint32_t)(so + r1i * GST + seg) * 2,
                  A + (size_t)(m0 + r1i) * K + k0 + seg, (m0 + r1i < M) ? 16 : 0);
        cpasync16(bs_u + (uint32_t)(so + r0i * GST + seg) * 2,
                  B + (size_t)(n0 + r0i) * K + k0 + seg, 16);
        cpasync16(bs_u + (uint32_t)(so + r1i * GST + seg) * 2,
                  B + (size_t)(n0 + r1i) * K + k0 + seg, 16);
        cp_commit();
    }

    int st_c = 0, st_p = 2;
    for (int c = 0; c < nch; ++c) {
        if (c + 1 < nch) cp_wait1(); else cp_wait0();
        __syncthreads();

        if (c + 2 < nch) {
            const int k0 = (c + 2) * 32;
            const int so = st_p * GSTG;
            cpasync16(as_u + (uint32_t)(so + r0i * GST + seg) * 2,
                      A + (size_t)(m0 + r0i) * K + k0 + seg, (m0 + r0i < M) ? 16 : 0);
            cpasync16(as_u + (uint32_t)(so + r1i * GST + seg) * 2,
                      A + (size_t)(m0 + r1i) * K + k0 + seg, (m0 + r1i < M) ? 16 : 0);
            cpasync16(bs_u + (uint32_t)(so + r0i * GST + seg) * 2,
                      B + (size_t)(n0 + r0i) * K + k0 + seg, 16);
            cpasync16(bs_u + (uint32_t)(so + r1i * GST + seg) * 2,
                      B + (size_t)(n0 + r1i) * K + k0 + seg, 16);
            cp_commit();
        }

        const uint32_t a_base = as_u + (uint32_t)(st_c * GSTG) * 2;
        const uint32_t b_base = bs_u + (uint32_t)(st_c * GSTG) * 2;

        #pragma unroll
        for (int kk = 0; kk < 2; ++kk) {
            const int kb = kk * 16;
            uint32_t afr[4][4], bfr[4][2];
            #pragma unroll
            for (int mi = 0; mi < 4; mi++) {
                int m = wm * 64 + mi * 16;
                uint32_t addr = a_base + (uint32_t)((m + lrowA) * GST + kb + lcolA) * 2;
                LDSM_X4(afr[mi][0], afr[mi][1], afr[mi][2], afr[mi][3], addr);
            }
            #pragma unroll
            for (int njp = 0; njp < 2; njp++) {
                int n = wn * 32 + njp * 16;
                uint32_t addr = b_base + (uint32_t)((n + lrowB) * GST + kb + lcolB) * 2;
                LDSM_X4(bfr[njp * 2][0], bfr[njp * 2][1],
                        bfr[njp * 2 + 1][0], bfr[njp * 2 + 1][1], addr);
            }
            #pragma unroll
            for (int mi = 0; mi < 4; mi++)
                #pragma unroll
                for (int nj = 0; nj < 4; nj++)
                    MMA_F16(acc[mi][nj], afr[mi], bfr[nj]);
        }
        st_c = (st_c == 2) ? 0 : st_c + 1;
        st_p = (st_p == 2) ? 0 : st_p + 1;
    }

    #pragma unroll
    for (int mi = 0; mi < 4; mi++) {
        int r0 = m0 + wm * 64 + mi * 16 + g;
        #pragma unroll
        for (int nj = 0; nj < 4; nj++) {
            int cb = n0 + wn * 32 + nj * 8 + 2 * t;
            #pragma unroll
            for (int half_ = 0; half_ < 2; half_++) {
                int gm = r0 + half_ * 8;
                if (gm >= M) continue;
                #pragma unroll
                for (int q = 0; q < 2; q++) {
                    int gn = cb + q;
                    if (gn >= N) continue;
                    float v = acc[mi][nj][half_ * 2 + q];
                    if (EPI == 1 || EPI == 2 || EPI == 3) v += bias[gn];
                    if (EPI == 2)
                        v = 0.5f * v * (1.0f + erff(v * 0.70710678118654752f));
                    if (EPI == 3)
                        Cf[(size_t)gm * ldc + gn] = v + res[(size_t)gm * ldc + gn];
                    else
                        Ch[(size_t)gm * ldc + gn] = __float2half_rn(v);
                }
            }
        }
    }
}

// ---------------- kg: Gt[z,j,d] = 0.125 * sum_m fc_w[m,j] K[m,d] -----------
// Double-buffered (2-stage) chunk pipeline.
#define KG_PS 2176   // 16*136 halfs per stage
#define KG_VS 1152   // 16*72 halfs per stage

__global__ void __launch_bounds__(256) kg_f16(const __half* __restrict__ Wp,
                                              const __half* __restrict__ qkv,
                                              __half* __restrict__ G)
{
    __shared__ __half Ps[2 * KG_PS];
    __shared__ __half Ks[2 * KG_VS];
    const int z = blockIdx.y, b = z / HEADS, h = z % HEADS;
    const __half* Kb = qkv + (size_t)b * SEQ * EMB3 + h * HD + EMB;
    const int m0 = blockIdx.x * 128;   // j range
    const int tid = threadIdx.x;
    const int warp = tid >> 5, lane = tid & 31;
    const int wm = warp >> 1, wn = warp & 1;
    const int g = lane >> 2, t = lane & 3;
    const uint32_t ps_u = (uint32_t)__cvta_generic_to_shared(Ps);
    const uint32_t vs_u = (uint32_t)__cvta_generic_to_shared(Ks);

    const int arow = (lane & 7) + ((lane >> 4) << 3);
    const int acol8 = ((lane >> 3) & 1) << 3;
    const int brow = (lane & 7) + (((lane >> 3) & 1) << 3);
    const int bcol8 = (lane >> 4) << 3;

    float acc[2][4][4];
    #pragma unroll
    for (int i = 0; i < 2; i++)
        #pragma unroll
        for (int j = 0; j < 4; j++)
            #pragma unroll
            for (int r = 0; r < 4; r++) acc[i][j][r] = 0.f;

    const int nch = KWPAD / 16;

    #define KG_LOAD(cc, st) do {                                               \
        const int _k0 = (cc) * 16;                                             \
        {                                                                      \
            int _r = tid >> 4, _sg = (tid & 15) * 8;                           \
            cpasync16(ps_u + (uint32_t)((st) * KG_PS + _r * 136 + _sg) * 2,    \
                      Wp + (size_t)(_k0 + _r) * SPAD + m0 + _sg,               \
                      (_k0 + _r < SEQ && m0 + _sg < SPAD) ? 16 : 0);           \
        }                                                                      \
        if (tid < 128) {                                                       \
            int _r = tid >> 3, _sg = (tid & 7) * 8;                            \
            cpasync16(vs_u + (uint32_t)((st) * KG_VS + _r * 72 + _sg) * 2,     \
                      Kb + (size_t)(_k0 + _r) * EMB3 + _sg,                    \
                      (_k0 + _r < SEQ) ? 16 : 0);                              \
        }                                                                      \
        cp_commit(); } while (0)

    KG_LOAD(0, 0);

    for (int c = 0; c < nch; ++c) {
        cp_wait0();
        __syncthreads();
        if (c + 1 < nch) KG_LOAD(c + 1, (c + 1) & 1);

        const int st = c & 1;
        const uint32_t ps_b = ps_u + (uint32_t)(st * KG_PS) * 2;
        const uint32_t vs_b = vs_u + (uint32_t)(st * KG_VS) * 2;

        uint32_t afr[2][4], bfr[4][2];
        #pragma unroll
        for (int mi = 0; mi < 2; mi++) {
            uint32_t addr = ps_b + (uint32_t)(arow * 136 + wm * 32 + mi * 16 + acol8) * 2;
            LDSM_X4_T(afr[mi][0], afr[mi][1], afr[mi][2], afr[mi][3], addr);
        }
        #pragma unroll
        for (int njp = 0; njp < 2; njp++) {
            uint32_t addr = vs_b + (uint32_t)(brow * 72 + wn * 32 + njp * 16 + bcol8) * 2;
            LDSM_X4_T(bfr[njp * 2][0], bfr[njp * 2][1],
                      bfr[njp * 2 + 1][0], bfr[njp * 2 + 1][1], addr);
        }
        #pragma unroll
        for (int mi = 0; mi < 2; mi++)
            #pragma unroll
            for (int nj = 0; nj < 4; nj++)
                MMA_F16(acc[mi][nj], afr[mi], bfr[nj]);
    }

    __half* Gz = G + (size_t)z * SPAD * HD;
    #pragma unroll
    for (int mi = 0; mi < 2; mi++) {
        int r0 = m0 + wm * 32 + mi * 16 + g;
        #pragma unroll
        for (int nj = 0; nj < 4; nj++) {
            int cb = wn * 32 + nj * 8 + 2 * t;
            #pragma unroll
            for (int half_ = 0; half_ < 2; half_++) {
                int gm = r0 + half_ * 8;
                if (gm >= SPAD) continue;
                #pragma unroll
                for (int q = 0; q < 2; q++)
                    Gz[(size_t)gm * HD + cb + q] =
                        __float2half_rn(acc[mi][nj][half_ * 2 + q] * 0.125f);
            }
        }
    }
}

// ===== qgs: A[z,n,j] = softmax_j( LN_j( sum_d Q[n,d] Gt[j,d] + fc_b ) ) ====
__global__ void __launch_bounds__(256) qgs_f16(
    const __half* __restrict__ qkv, const __half* __restrict__ G,
    const float* __restrict__ fc_b,
    const float* __restrict__ ln_g, const float* __restrict__ ln_b,
    __half* __restrict__ Aout)
{
    __shared__ __half Qs[64 * 72];
    __shared__ __half Gs[224 * 72];
    __shared__ float red_s[64 * 4];
    __shared__ float red_ss[64 * 4];
    __shared__ float biasf[224], lngs[224], lnbs[224];

    const int z = blockIdx.y, b = z / HEADS, h = z % HEADS;
    const int m0 = blockIdx.x * 64;
    const __half* qb = qkv + (size_t)b * SEQ * EMB3 + h * HD;
    const __half* Gb = G + (size_t)z * SPAD * HD;

    const int tid = threadIdx.x;
    const int warp = tid >> 5, lane = tid & 31;
    const int wm = warp >> 2, wn = warp & 3;
    const int g = lane >> 2, t = lane & 3;
    const uint32_t qs_u = (uint32_t)__cvta_generic_to_shared(Qs);
    const uint32_t gs_u = (uint32_t)__cvta_generic_to_shared(Gs);

    for (int i = tid; i < 224; i += 256) {
        biasf[i] = (i < KW) ? fc_b[i] : 0.f;
        lngs[i]  = (i < KW) ? ln_g[i] : 0.f;
        lnbs[i]  = (i < KW) ? ln_b[i] : 0.f;
    }

    #pragma unroll
    for (int i = 0; i < 2; i++) {
        int f = tid + i * 256;
        int r = f >> 3, sg = (f & 7) * 8;
        cpasync16(qs_u + (uint32_t)(r * 72 + sg) * 2,
                  qb + (size_t)(m0 + r) * EMB3 + sg, (m0 + r < SEQ) ? 16 : 0);
    }
    #pragma unroll
    for (int i = 0; i < 7; i++) {
        int f = tid + i * 256;
        int r = f >> 3, sg = (f & 7) * 8;
        cpasync16(gs_u + (uint32_t)(r * 72 + sg) * 2,
                  Gb + (size_t)r * HD + sg, 16);
    }
    cp_commit(); cp_wait0();
    __syncthreads();

    float acc[2][7][4];
    #pragma unroll
    for (int i = 0; i < 2; i++)
        #pragma unroll
        for (int j = 0; j < 7; j++)
            #pragma unroll
            for (int r = 0; r < 4; r++) acc[i][j][r] = 0.f;

    const uint32_t* qs32 = (const uint32_t*)Qs;
    const uint32_t* gs32 = (const uint32_t*)Gs;
    #pragma unroll
    for (int kk = 0; kk < 4; ++kk) {
        const int kb2 = kk * 8;
        uint32_t afr[2][4], bfr[7][2];
        #pragma unroll
        for (int mi = 0; mi < 2; mi++) {
            int m = wm * 32 + mi * 16 + g;
            afr[mi][0] = qs32[(m    ) * 36 + kb2 + t];
            afr[mi][1] = qs32[(m + 8) * 36 + kb2 + t];
            afr[mi][2] = qs32[(m    ) * 36 + kb2 + t + 4];
            afr[mi][3] = qs32[(m + 8) * 36 + kb2 + t + 4];
        }
        #pragma unroll
        for (int nj = 0; nj < 7; nj++) {
            int n = wn * 56 + nj * 8 + g;
            bfr[nj][0] = gs32[n * 36 + kb2 + t];
            bfr[nj][1] = gs32[n * 36 + kb2 + t + 4];
        }
        #pragma unroll
        for (int mi = 0; mi < 2; mi++)
            #pragma unroll
            for (int nj = 0; nj < 7; nj++)
                MMA_F16(acc[mi][nj], afr[mi], bfr[nj]);
    }

    // ---- epilogue: +bias, LN(row over KW), softmax(row) ----
    float mu_[2][2], inv_[2][2];
    #pragma unroll
    for (int mi = 0; mi < 2; mi++)
        #pragma unroll
        for (int hf = 0; hf < 2; hf++) {
            float s = 0.f, ss = 0.f;
            #pragma unroll
            for (int nj = 0; nj < 7; nj++)
                #pragma unroll
                for (int q = 0; q < 2; q++) {
                    int gn = wn * 56 + nj * 8 + 2 * t + q;
                    if (gn < KW) {
                        float v = acc[mi][nj][hf * 2 + q] + biasf[gn];
                        acc[mi][nj][hf * 2 + q] = v;
                        s += v; ss += v * v;
                    }
                }
            s  += __shfl_xor_sync(0xffffffffu, s, 1);
            s  += __shfl_xor_sync(0xffffffffu, s, 2);
            ss += __shfl_xor_sync(0xffffffffu, ss, 1);
            ss += __shfl_xor_sync(0xffffffffu, ss, 2);
            if (t == 0) {
                int row = wm * 32 + mi * 16 + g + 8 * hf;
                red_s [row * 4 + wn] = s;
                red_ss[row * 4 + wn] = ss;
            }
        }
    __syncthreads();
    #pragma unroll
    for (int mi = 0; mi < 2; mi++)
        #pragma unroll
        for (int hf = 0; hf < 2; hf++) {
            int row = wm * 32 + mi * 16 + g + 8 * hf;
            float s  = red_s [row * 4] + red_s [row * 4 + 1]
                     + red_s [row * 4 + 2] + red_s [row * 4 + 3];
            float ss = red_ss[row * 4] + red_ss[row * 4 + 1]
                     + red_ss[row * 4 + 2] + red_ss[row * 4 + 3];
            float mu = s * (1.0f / KW);
            float var = ss * (1.0f / KW) - mu * mu;
            mu_[mi][hf] = mu;
            inv_[mi][hf] = rsqrtf(var + 1e-5f);
        }
    __syncthreads();
    float mx_[2][2];
    #pragma unroll
    for (int mi = 0; mi < 2; mi++)
        #pragma unroll
        for (int hf = 0; hf < 2; hf++) {
            float mx = -1e30f;
            #pragma unroll
            for (int nj = 0; nj < 7; nj++)
                #pragma unroll
                for (int q = 0; q < 2; q++) {
                    int gn = wn * 56 + nj * 8 + 2 * t + q;
                    if (gn < KW) {
                        float zv = (acc[mi][nj][hf * 2 + q] - mu_[mi][hf]) * inv_[mi][hf]
                                   * lngs[gn] + lnbs[gn];
                        acc[mi][nj][hf * 2 + q] = zv;
                        mx = fmaxf(mx, zv);
                    }
                }
            mx = fmaxf(mx, __shfl_xor_sync(0xffffffffu, mx, 1));
            mx = fmaxf(mx, __shfl_xor_sync(0xffffffffu, mx, 2));
            if (t == 0) {
                int row = wm * 32 + mi * 16 + g + 8 * hf;
                red_s[row * 4 + wn] = mx;
            }
        }
    __syncthreads();
    #pragma unroll
    for (int mi = 0; mi < 2; mi++)
        #pragma unroll
        for (int hf = 0; hf < 2; hf++) {
            int row = wm * 32 + mi * 16 + g + 8 * hf;
            mx_[mi][hf] = fmaxf(fmaxf(red_s[row * 4], red_s[row * 4 + 1]),
                                fmaxf(red_s[row * 4 + 2], red_s[row * 4 + 3]));
        }
    __syncthreads();
    float rinv_[2][2];
    #pragma unroll
    for (int mi = 0; mi < 2; mi++)
        #pragma unroll
        for (int hf = 0; hf < 2; hf++) {
            float s = 0.f;
            #pragma unroll
            for (int nj = 0; nj < 7; nj++)
                #pragma unroll
                for (int q = 0; q < 2; q++) {
                    int gn = wn * 56 + nj * 8 + 2 * t + q;
                    if (gn < KW) {
                        float e = __expf(acc[mi][nj][hf * 2 + q] - mx_[mi][hf]);
                        acc[mi][nj][hf * 2 + q] = e;
                        s += e;
                    }
                }
            s += __shfl_xor_sync(0xffffffffu, s, 1);
            s += __shfl_xor_sync(0xffffffffu, s, 2);
            if (t == 0) {
                int row = wm * 32 + mi * 16 + g + 8 * hf;
                red_s[row * 4 + wn] = s;
            }
        }
    __syncthreads();
    #pragma unroll
    for (int mi = 0; mi < 2; mi++)
        #pragma unroll
        for (int hf = 0; hf < 2; hf++) {
            int row = wm * 32 + mi * 16 + g + 8 * hf;
            rinv_[mi][hf] = 1.0f / (red_s[row * 4] + red_s[row * 4 + 1]
                                  + red_s[row * 4 + 2] + red_s[row * 4 + 3]);
        }
    __half* Az = Aout + (size_t)z * SEQ * SPAD;
    #pragma unroll
    for (int mi = 0; mi < 2; mi++)
        #pragma unroll
        for (int hf = 0; hf < 2; hf++) {
            int gm = m0 + wm * 32 + mi * 16 + g + 8 * hf;
            if (gm >= SEQ) continue;
            #pragma unroll
            for (int nj = 0; nj < 7; nj++) {
                int gn0 = wn * 56 + nj * 8 + 2 * t;
                float p0 = (gn0     < KW) ? acc[mi][nj][hf * 2    ] * rinv_[mi][hf] : 0.f;
                float p1 = (gn0 + 1 < KW) ? acc[mi][nj][hf * 2 + 1] * rinv_[mi][hf] : 0.f;
                *(__half2*)(Az + (size_t)gm * SPAD + gn0) = __floats2half2_rn(p0, p1);
            }
        }
}

// ---------------- P^T V fp16 (double-buffered) ------------------------------
__global__ void __launch_bounds__(256) pv_f16(const __half* __restrict__ A,
                                              const __half* __restrict__ qkv,
                                              __half* __restrict__ y)
{
    __shared__ __half Ps[2 * KG_PS];
    __shared__ __half Vs[2 * KG_VS];
    const int z = blockIdx.y, b = z / HEADS, h = z % HEADS;
    const __half* Ab = A + (size_t)z * SEQ * SPAD;
    const __half* Vb = qkv + (size_t)b * SEQ * EMB3 + h * HD + 2 * EMB;
    const int m0 = blockIdx.x * 128;
    const int tid = threadIdx.x;
    const int warp = tid >> 5, lane = tid & 31;
    const int wm = warp >> 1, wn = warp & 1;
    const int g = lane >> 2, t = lane & 3;
    const uint32_t ps_u = (uint32_t)__cvta_generic_to_shared(Ps);
    const uint32_t vs_u = (uint32_t)__cvta_generic_to_shared(Vs);

    const int arow = (lane & 7) + ((lane >> 4) << 3);
    const int acol8 = ((lane >> 3) & 1) << 3;
    const int brow = (lane & 7) + (((lane >> 3) & 1) << 3);
    const int bcol8 = (lane >> 4) << 3;

    float acc[2][4][4];
    #pragma unroll
    for (int i = 0; i < 2; i++)
        #pragma unroll
        for (int j = 0; j < 4; j++)
            #pragma unroll
            for (int r = 0; r < 4; r++) acc[i][j][r] = 0.f;

    const int nch = KWPAD / 16;

    #define PV_LOAD(cc, st) do {                                               \
        const int _k0 = (cc) * 16;                                             \
        {                                                                      \
            int _r = tid >> 4, _sg = (tid & 15) * 8;                           \
            cpasync16(ps_u + (uint32_t)((st) * KG_PS + _r * 136 + _sg) * 2,    \
                      Ab + (size_t)(_k0 + _r) * SPAD + m0 + _sg,               \
                      (_k0 + _r < SEQ && m0 + _sg < SPAD) ? 16 : 0);           \
        }                                                                      \
        if (tid < 128) {                                                       \
            int _r = tid >> 3, _sg = (tid & 7) * 8;                            \
            cpasync16(vs_u + (uint32_t)((st) * KG_VS + _r * 72 + _sg) * 2,     \
                      Vb + (size_t)(_k0 + _r) * EMB3 + _sg,                    \
                      (_k0 + _r < SEQ) ? 16 : 0);                              \
        }                                                                      \
        cp_commit(); } while (0)

    PV_LOAD(0, 0);

    for (int c = 0; c < nch; ++c) {
        cp_wait0();
        __syncthreads();
        if (c + 1 < nch) PV_LOAD(c + 1, (c + 1) & 1);

        const int st = c & 1;
        const uint32_t ps_b = ps_u + (uint32_t)(st * KG_PS) * 2;
        const uint32_t vs_b = vs_u + (uint32_t)(st * KG_VS) * 2;

        uint32_t afr[2][4], bfr[4][2];
        #pragma unroll
        for (int mi = 0; mi < 2; mi++) {
            uint32_t addr = ps_b + (uint32_t)(arow * 136 + wm * 32 + mi * 16 + acol8) * 2;
            LDSM_X4_T(afr[mi][0], afr[mi][1], afr[mi][2], afr[mi][3], addr);
        }
        #pragma unroll
        for (int njp = 0; njp < 2; njp++) {
            uint32_t addr = vs_b + (uint32_t)(brow * 72 + wn * 32 + njp * 16 + bcol8) * 2;
            LDSM_X4_T(bfr[njp * 2][0], bfr[njp * 2][1],
                      bfr[njp * 2 + 1][0], bfr[njp * 2 + 1][1], addr);
        }
        #pragma unroll
        for (int mi = 0; mi < 2; mi++)
            #pragma unroll
            for (int nj = 0; nj < 4; nj++)
                MMA_F16(acc[mi][nj], afr[mi], bfr[nj]);
    }

    __half* yz = y + (size_t)z * KW * HD;
    #pragma unroll
    for (int mi = 0; mi < 2; mi++) {
        int r0 = m0 + wm * 32 + mi * 16 + g;
        #pragma unroll
        for (int nj = 0; nj < 4; nj++) {
            int cb = wn * 32 + nj * 8 + 2 * t;
            #pragma unroll
            for (int half_ = 0; half_ < 2; half_++) {
                int gm = r0 + half_ * 8;
                if (gm >= KW) continue;
                #pragma unroll
                for (int q = 0; q < 2; q++)
                    yz[(size_t)gm * HD + cb + q] =
                        __float2half_rn(acc[mi][nj][half_ * 2 + q]);
            }
        }
    }
}

// --------- fc2: x1 += Wt @ y + bias (double-buffered) ----------------------
#define OUT_AS 3072   // 128*24 halfs per stage
#define OUT_YS 1152   // 16*72 halfs per stage

__global__ void __launch_bounds__(256) out_f16(const __half* __restrict__ Wt,
                                               const __half* __restrict__ y,
                                               const float* __restrict__ bias,
                                               float* __restrict__ x1)
{
    __shared__ __half As[2 * OUT_AS];
    __shared__ __half Ys[2 * OUT_YS];
    const int z = blockIdx.y, b = z / HEADS, h = z % HEADS;
    const __half* yb = y + (size_t)z * KW * HD;
    const int m0 = blockIdx.x * 128;
    const int tid = threadIdx.x;
    const int warp = tid >> 5, lane = tid & 31;
    const int wm = warp >> 1, wn = warp & 1;
    const int g = lane >> 2, t = lane & 3;
    const uint32_t as_u = (uint32_t)__cvta_generic_to_shared(As);
    const uint32_t ys_u = (uint32_t)__cvta_generic_to_shared(Ys);

    const int brow = (lane & 7) + (((lane >> 3) & 1) << 3);
    const int bcol8 = (lane >> 4) << 3;

    float acc[2][4][4];
    #pragma unroll
    for (int i = 0; i < 2; i++)
        #pragma unroll
        for (int j = 0; j < 4; j++)
            #pragma unroll
            for (int r = 0; r < 4; r++) acc[i][j][r] = 0.f;

    const int nch = KWPAD / 16;

    #define OUT_LOAD(cc, st) do {                                              \
        const int _k0 = (cc) * 16;                                             \
        {                                                                      \
            int _r = tid >> 1, _sg = (tid & 1) * 8;                            \
            cpasync16(as_u + (uint32_t)((st) * OUT_AS + _r * 24 + _sg) * 2,    \
                      Wt + (size_t)(m0 + _r) * KWPAD + _k0 + _sg, 16);         \
        }                                                                      \
        if (tid < 128) {                                                       \
            int _r = tid >> 3, _sg = (tid & 7) * 8;                            \
            cpasync16(ys_u + (uint32_t)((st) * OUT_YS + _r * 72 + _sg) * 2,    \
                      yb + (size_t)(_k0 + _r) * HD + _sg,                      \
                      (_k0 + _r < KW) ? 16 : 0);                               \
        }                                                                      \
        cp_commit(); } while (0)

    OUT_LOAD(0, 0);

    for (int c = 0; c < nch; ++c) {
        cp_wait0();
        __syncthreads();
        if (c + 1 < nch) OUT_LOAD(c + 1, (c + 1) & 1);

        const int st = c & 1;
        const uint32_t* as32 = (const uint32_t*)(As + st * OUT_AS);
        const uint32_t ys_b = ys_u + (uint32_t)(st * OUT_YS) * 2;

        uint32_t afr[2][4], bfr[4][2];
        #pragma unroll
        for (int mi = 0; mi < 2; mi++) {
            int m = wm * 32 + mi * 16 + g;
            afr[mi][0] = as32[(m    ) * 12 + t];
            afr[mi][1] = as32[(m + 8) * 12 + t];
            afr[mi][2] = as32[(m    ) * 12 + t + 4];
            afr[mi][3] = as32[(m + 8) * 12 + t + 4];
        }
        #pragma unroll
        for (int njp = 0; njp < 2; njp++) {
            uint32_t addr = ys_b + (uint32_t)(brow * 72 + wn * 32 + njp * 16 + bcol8) * 2;
            LDSM_X4_T(bfr[njp * 2][0], bfr[njp * 2][1],
                      bfr[njp * 2 + 1][0], bfr[njp * 2 + 1][1], addr);
        }
        #pragma unroll
        for (int mi = 0; mi < 2; mi++)
            #pragma unroll
            for (int nj = 0; nj < 4; nj++)
                MMA_F16(acc[mi][nj], afr[mi], bfr[nj]);
    }

    #pragma unroll
    for (int mi = 0; mi < 2; mi++) {
        int r0 = m0 + wm * 32 + mi * 16 + g;
        #pragma unroll
        for (int nj = 0; nj < 4; nj++) {
            int cb = wn * 32 + nj * 8 + 2 * t;
            #pragma unroll
            for (int half_ = 0; half_ < 2; half_++) {
                int gm = r0 + half_ * 8;
                if (gm >= SEQ) continue;
                float bv = bias[gm];
                #pragma unroll
                for (int q = 0; q < 2; q++) {
                    size_t idx = ((size_t)(b * SEQ + gm)) * EMB + h * HD + cb + q;
                    x1[idx] += acc[mi][nj][half_ * 2 + q] + bv;
                }
            }
        }
    }
}

// ---------------- launch ----------------
extern "C" void kernel_launch(void* const* d_in, const int* in_sizes, int n_in,
                              void* d_out, int out_size) {
    (void)in_sizes; (void)n_in; (void)out_size;
    const float* x         = (const float*)d_in[0];
    const float* qkv_w     = (const float*)d_in[1];
    const float* fc_w      = (const float*)d_in[2];
    const float* fc_b      = (const float*)d_in[3];
    const float* attn_ln_g = (const float*)d_in[4];
    const float* attn_ln_b = (const float*)d_in[5];
    const float* fc2_w     = (const float*)d_in[6];
    const float* fc2_b     = (const float*)d_in[7];
    const float* mlp_w1    = (const float*)d_in[8];
    const float* mlp_b1    = (const float*)d_in[9];
    const float* mlp_w2    = (const float*)d_in[10];
    const float* mlp_b2    = (const float*)d_in[11];
    const float* f_ln_g    = (const float*)d_in[12];
    const float* f_ln_b    = (const float*)d_in[13];
    const float* gl_ln_g   = (const float*)d_in[14];
    const float* gl_ln_b   = (const float*)d_in[15];

    float *px1, *px2;
    __half *pxn, *pqkv, *pA, *pG, *py, *ph;
    __half *pwqkv, *pwfcp, *pw1, *pw2, *pwfc2t;
    cudaGetSymbolAddress((void**)&px1,  g_x1);
    cudaGetSymbolAddress((void**)&px2,  g_x2);
    cudaGetSymbolAddress((void**)&pxn,  g_xn);
    cudaGetSymbolAddress((void**)&pqkv, g_qkv);
    cudaGetSymbolAddress((void**)&pA,   g_A);
    cudaGetSymbolAddress((void**)&pG,   g_G);
    cudaGetSymbolAddress((void**)&py,   g_y);
    cudaGetSymbolAddress((void**)&ph,   g_h);
    cudaGetSymbolAddress((void**)&pwqkv,  g_wqkv);
    cudaGetSymbolAddress((void**)&pwfcp,  g_wfcp);
    cudaGetSymbolAddress((void**)&pw1,    g_w1);
    cudaGetSymbolAddress((void**)&pw2,    g_w2);
    cudaGetSymbolAddress((void**)&pwfc2t, g_wfc2t);

    const int NE = TOK * EMB;

    prep_wT<<<CDIV(EMB*EMB3, 256), 256>>>(qkv_w, pwqkv, EMB, EMB3);
    prep_wT<<<CDIV(EMB*HIDDEN, 256), 256>>>(mlp_w1, pw1, EMB, HIDDEN);
    prep_wT<<<CDIV(HIDDEN*EMB, 256), 256>>>(mlp_w2, pw2, HIDDEN, EMB);
    prep_fcpad<<<CDIV(SPAD*SPAD, 256), 256>>>(fc_w, pwfcp);
    prep_fc2T<<<CDIV(256*KWPAD, 256), 256>>>(fc2_w, pwfc2t);

    init_copy<<<CDIV(NE, 256), 256>>>(x, px1, px2, NE);

    for (int l = 0; l < NLAYERS; ++l) {
        // y1 = x1 + attention(LN_f(x2))
        ln_row768<<<TOK, 256>>>(px2, f_ln_g + l * EMB, f_ln_b + l * EMB, pxn);
        gemm_f16<4><<<dim3(EMB3/128, CDIV(TOK,128)), 256>>>(
            pxn, pwqkv, nullptr, nullptr, pqkv, nullptr, EMB3, TOK, EMB3, EMB);
        kg_f16<<<dim3(2, BH), 256>>>(pwfcp, pqkv, pG);
        qgs_f16<<<dim3(CDIV(SEQ,64), BH), 256>>>(
            pqkv, pG, fc_b, attn_ln_g, attn_ln_b, pA);
        pv_f16<<<dim3(2, BH), 256>>>(pA, pqkv, py);
        out_f16<<<dim3(2, BH), 256>>>(pwfc2t, py, fc2_b, px1);
        // y2 = x2 + mlp(LN_g(y1))
        ln_row768<<<TOK, 256>>>(px1, gl_ln_g + l * EMB, gl_ln_b + l * EMB, pxn);
        gemm_f16<2><<<dim3(HIDDEN/128, CDIV(TOK,128)), 256>>>(
            pxn, pw1, mlp_b1, nullptr, ph, nullptr, HIDDEN, TOK, HIDDEN, EMB);
        gemm_f16<3><<<dim3(EMB/128, CDIV(TOK,128)), 256>>>(
            ph, pw2, mlp_b2, px2, nullptr, px2, EMB, TOK, EMB, HIDDEN);
    }

    finalize_k<<<CDIV(NE, 256), 256>>>(px1, px2, (float*)d_out, NE);
}